// round 1
// baseline (speedup 1.0000x reference)
#include <cuda_runtime.h>
#include <math.h>

// ---------------------------------------------------------------------------
// Problem constants (B,T,D,H,L,V = 4,1024,512,8,6,128 ; DFF = 2048)
// ---------------------------------------------------------------------------
namespace cfg {
constexpr int B = 4, T = 1024, D = 512, H = 8, L = 6, V = 128, DFF = 2048;
constexpr int NT = B * T;     // 4096 token rows
constexpr int HD = H * D;     // 4096 concat width
}

using namespace cfg;

// ---------------------------------------------------------------------------
// Static device scratch (no dynamic allocation allowed)
// ---------------------------------------------------------------------------
__device__ float g_x[NT * D];                 //  8 MB residual stream
__device__ float g_q[B * H * T * D];          // 64 MB
__device__ float g_k[B * H * T * D];          // 64 MB
__device__ float g_v[B * H * T * D];          // 64 MB
__device__ float g_sc[(long long)B * H * T * T]; // 134 MB attention scores
__device__ float g_oc[NT * HD];               // 64 MB concat heads
__device__ float g_h1[NT * DFF];              // 32 MB ffn hidden
__device__ float g_t2[NT * D];                //  8 MB per-sublayer output
__device__ float g_xf[NT * D];                //  8 MB final LN
__device__ float g_logits[NT * V];            //  2 MB
__device__ float g_rowloss[NT];
__device__ float g_loss[1];

// ---------------------------------------------------------------------------
// Generic tiled SGEMM: C[M,N] = A[M,K] @ B (+bias)(+relu), optional B^T.
// Two-level batching: grid.z = outer*innerB + inner, with independent strides.
// All used M,N are multiples of 128 and K multiples of 16 -> no bounds checks.
// ---------------------------------------------------------------------------
constexpr int BM = 128, BN = 128, BK = 16;

template <bool TRANSB, bool RELU, bool BIAS>
__global__ __launch_bounds__(256) void gemm_k(
    const float* __restrict__ A, const float* __restrict__ Bm,
    const float* __restrict__ bias, float* __restrict__ C,
    int M, int N, int K, int ldc,
    long long aO, long long aI, long long bO, long long bI,
    long long cO, long long cI, long long biasI, int innerB)
{
    const int z = blockIdx.z;
    const int outer = z / innerB;
    const int inner = z - outer * innerB;
    A  += outer * aO + inner * aI;
    Bm += outer * bO + inner * bI;
    C  += outer * cO + inner * cI;
    const float* bp = nullptr;
    if (BIAS) bp = bias + inner * biasI;

    __shared__ __align__(16) float As[BK][BM + 4];
    __shared__ __align__(16) float Bs[BK][BN + 4];

    const int tid = threadIdx.x;
    const int tx = tid & 15;   // col group
    const int ty = tid >> 4;   // row group
    const int m0 = blockIdx.y * BM;
    const int n0 = blockIdx.x * BN;

    float acc[8][8];
#pragma unroll
    for (int i = 0; i < 8; i++)
#pragma unroll
        for (int j = 0; j < 8; j++) acc[i][j] = 0.f;

    for (int k0 = 0; k0 < K; k0 += BK) {
        // --- load A tile (128 x 16), store transposed As[k][m] ---
#pragma unroll
        for (int it = 0; it < 2; it++) {
            int lin = tid + it * 256;
            int row = lin >> 2;
            int kv = (lin & 3) << 2;
            float4 va = *(const float4*)(A + (long long)(m0 + row) * K + (k0 + kv));
            As[kv + 0][row] = va.x;
            As[kv + 1][row] = va.y;
            As[kv + 2][row] = va.z;
            As[kv + 3][row] = va.w;
        }
        // --- load B tile ---
        if (!TRANSB) {
#pragma unroll
            for (int it = 0; it < 2; it++) {
                int lin = tid + it * 256;
                int kr = lin >> 5;
                int nv = (lin & 31) << 2;
                float4 vb = *(const float4*)(Bm + (long long)(k0 + kr) * N + (n0 + nv));
                *(float4*)&Bs[kr][nv] = vb;
            }
        } else {
            // B is [N,K] row-major; Bs[k][n] = B[n, k]
#pragma unroll
            for (int it = 0; it < 2; it++) {
                int lin = tid + it * 256;
                int nr = lin >> 2;
                int kv = (lin & 3) << 2;
                float4 vb = *(const float4*)(Bm + (long long)(n0 + nr) * K + (k0 + kv));
                Bs[kv + 0][nr] = vb.x;
                Bs[kv + 1][nr] = vb.y;
                Bs[kv + 2][nr] = vb.z;
                Bs[kv + 3][nr] = vb.w;
            }
        }
        __syncthreads();

#pragma unroll
        for (int kk = 0; kk < BK; kk++) {
            float4 a0 = *(const float4*)&As[kk][ty * 8];
            float4 a1 = *(const float4*)&As[kk][ty * 8 + 4];
            float4 b0 = *(const float4*)&Bs[kk][tx * 8];
            float4 b1 = *(const float4*)&Bs[kk][tx * 8 + 4];
            float a[8] = {a0.x, a0.y, a0.z, a0.w, a1.x, a1.y, a1.z, a1.w};
            float b[8] = {b0.x, b0.y, b0.z, b0.w, b1.x, b1.y, b1.z, b1.w};
#pragma unroll
            for (int i = 0; i < 8; i++)
#pragma unroll
                for (int j = 0; j < 8; j++) acc[i][j] += a[i] * b[j];
        }
        __syncthreads();
    }

#pragma unroll
    for (int i = 0; i < 8; i++) {
        const int m = m0 + ty * 8 + i;
        float vals[8];
#pragma unroll
        for (int j = 0; j < 8; j++) {
            float v = acc[i][j];
            if (BIAS) v += bp[n0 + tx * 8 + j];
            if (RELU) v = fmaxf(v, 0.f);
            vals[j] = v;
        }
        *(float4*)(C + (long long)m * ldc + n0 + tx * 8) =
            make_float4(vals[0], vals[1], vals[2], vals[3]);
        *(float4*)(C + (long long)m * ldc + n0 + tx * 8 + 4) =
            make_float4(vals[4], vals[5], vals[6], vals[7]);
    }
}

// ---------------------------------------------------------------------------
// Embedding gather: x[b,t,:] = emb[tokens[b,t], :]
// ---------------------------------------------------------------------------
__global__ void embed_k(const int* __restrict__ tok, const float* __restrict__ emb,
                        float* __restrict__ x)
{
    int i = blockIdx.x * blockDim.x + threadIdx.x;
    if (i >= NT * D) return;
    int r = i / D;
    int d = i - r * D;
    x[i] = emb[(long long)tok[r] * D + d];
}

// ---------------------------------------------------------------------------
// Causal softmax over scores row (no 1/sqrt(d) scaling — faithful to source).
// One block per (b,h,t) row; masked tail written as 0.
// ---------------------------------------------------------------------------
__global__ void softmax_k(float* __restrict__ sc)
{
    const long long r = blockIdx.x;
    const int t = (int)(r & (T - 1));
    float* row = sc + r * T;
    const int len = t + 1;
    __shared__ float buf[T];
    __shared__ float red[256];
    const int tid = threadIdx.x;

    float m = -1e30f;
    for (int s = tid; s < len; s += 256) {
        float v = row[s];
        buf[s] = v;
        m = fmaxf(m, v);
    }
    red[tid] = m;
    __syncthreads();
    for (int o = 128; o; o >>= 1) {
        if (tid < o) red[tid] = fmaxf(red[tid], red[tid + o]);
        __syncthreads();
    }
    m = red[0];
    __syncthreads();

    float sum = 0.f;
    for (int s = tid; s < len; s += 256) {
        float e = expf(buf[s] - m);
        buf[s] = e;
        sum += e;
    }
    red[tid] = sum;
    __syncthreads();
    for (int o = 128; o; o >>= 1) {
        if (tid < o) red[tid] += red[tid + o];
        __syncthreads();
    }
    const float inv = 1.f / red[0];
    for (int s = tid; s < T; s += 256)
        row[s] = (s < len) ? buf[s] * inv : 0.f;
}

// ---------------------------------------------------------------------------
// out[r,:] = LN(xin[r,:] + (a ? a[r,:] : 0)) * g + b    (eps = 1e-5)
// One block per row. Safe in-place (row cached in smem).
// ---------------------------------------------------------------------------
__global__ void addln_k(const float* __restrict__ xin, const float* __restrict__ a,
                        const float* __restrict__ g, const float* __restrict__ b,
                        float* __restrict__ out)
{
    const long long r = blockIdx.x;
    __shared__ float buf[D];
    __shared__ float red[256];
    const int tid = threadIdx.x;

    float s = 0.f;
    for (int d = tid; d < D; d += 256) {
        float v = xin[r * D + d];
        if (a) v += a[r * D + d];
        buf[d] = v;
        s += v;
    }
    red[tid] = s;
    __syncthreads();
    for (int o = 128; o; o >>= 1) {
        if (tid < o) red[tid] += red[tid + o];
        __syncthreads();
    }
    const float mean = red[0] * (1.f / D);
    __syncthreads();

    float vs = 0.f;
    for (int d = tid; d < D; d += 256) {
        float dv = buf[d] - mean;
        vs += dv * dv;
    }
    red[tid] = vs;
    __syncthreads();
    for (int o = 128; o; o >>= 1) {
        if (tid < o) red[tid] += red[tid + o];
        __syncthreads();
    }
    const float rstd = rsqrtf(red[0] * (1.f / D) + 1e-5f);
    for (int d = tid; d < D; d += 256)
        out[r * D + d] = (buf[d] - mean) * rstd * g[d] + b[d];
}

// ---------------------------------------------------------------------------
// Cross-entropy: per-row NLL, then deterministic single-block reduction.
// ---------------------------------------------------------------------------
__global__ void lossrow_k(const float* __restrict__ logits, const int* __restrict__ labels,
                          float* __restrict__ rowloss)
{
    const int r = blockIdx.x;
    const int tid = threadIdx.x;   // V = 128 threads
    __shared__ float red[V];
    const float v = logits[(long long)r * V + tid];
    red[tid] = v;
    __syncthreads();
    for (int o = 64; o; o >>= 1) {
        if (tid < o) red[tid] = fmaxf(red[tid], red[tid + o]);
        __syncthreads();
    }
    const float m = red[0];
    __syncthreads();
    red[tid] = expf(v - m);
    __syncthreads();
    for (int o = 64; o; o >>= 1) {
        if (tid < o) red[tid] += red[tid + o];
        __syncthreads();
    }
    if (tid == 0) {
        int lab = labels[r];
        rowloss[r] = -(logits[(long long)r * V + lab] - m - logf(red[0]));
    }
}

__global__ void lossred_k(const float* __restrict__ rowloss, float* __restrict__ loss)
{
    __shared__ float red[1024];
    const int tid = threadIdx.x;
    float s = 0.f;
    for (int i = tid; i < NT; i += 1024) s += rowloss[i];
    red[tid] = s;
    __syncthreads();
    for (int o = 512; o; o >>= 1) {
        if (tid < o) red[tid] += red[tid + o];
        __syncthreads();
    }
    if (tid == 0) loss[0] = red[0] / (float)NT;
}

// ---------------------------------------------------------------------------
// Output: flattened (logits, loss) tuple, adaptive to out_size.
// ---------------------------------------------------------------------------
__global__ void writeout_k(const float* __restrict__ logits, const float* __restrict__ loss,
                           float* __restrict__ out, int out_size)
{
    int i = blockIdx.x * blockDim.x + threadIdx.x;
    if (i >= out_size) return;
    const int NL = NT * V;
    if (out_size >= NL) out[i] = (i < NL) ? logits[i] : loss[0];
    else out[i] = loss[0];
}

// ---------------------------------------------------------------------------
// Host orchestration
// ---------------------------------------------------------------------------
extern "C" void kernel_launch(void* const* d_in, const int* in_sizes, int n_in,
                              void* d_out, int out_size)
{
    const int*   tokens = (const int*)d_in[0];
    const int*   labels = (const int*)d_in[1];
    const float* emb    = (const float*)d_in[2];
    const float* Wq     = (const float*)d_in[3];
    const float* bq     = (const float*)d_in[4];
    const float* Wk     = (const float*)d_in[5];
    const float* bk     = (const float*)d_in[6];
    const float* Wv     = (const float*)d_in[7];
    const float* bv     = (const float*)d_in[8];
    const float* Wo     = (const float*)d_in[9];
    const float* bo     = (const float*)d_in[10];
    const float* ln1g   = (const float*)d_in[11];
    const float* ln1b   = (const float*)d_in[12];
    const float* W1     = (const float*)d_in[13];
    const float* b1     = (const float*)d_in[14];
    const float* W2     = (const float*)d_in[15];
    const float* b2     = (const float*)d_in[16];
    const float* ln2g   = (const float*)d_in[17];
    const float* ln2b   = (const float*)d_in[18];
    const float* lnfg   = (const float*)d_in[19];
    const float* lnfb   = (const float*)d_in[20];
    const float* Wout   = (const float*)d_in[21];
    const float* bout   = (const float*)d_in[22];

    float *x, *q, *k, *v, *sc, *oc, *h1, *t2, *xf, *logits, *rowloss, *loss;
    cudaGetSymbolAddress((void**)&x, g_x);
    cudaGetSymbolAddress((void**)&q, g_q);
    cudaGetSymbolAddress((void**)&k, g_k);
    cudaGetSymbolAddress((void**)&v, g_v);
    cudaGetSymbolAddress((void**)&sc, g_sc);
    cudaGetSymbolAddress((void**)&oc, g_oc);
    cudaGetSymbolAddress((void**)&h1, g_h1);
    cudaGetSymbolAddress((void**)&t2, g_t2);
    cudaGetSymbolAddress((void**)&xf, g_xf);
    cudaGetSymbolAddress((void**)&logits, g_logits);
    cudaGetSymbolAddress((void**)&rowloss, g_rowloss);
    cudaGetSymbolAddress((void**)&loss, g_loss);

    // 1. embedding gather
    embed_k<<<(NT * D + 255) / 256, 256>>>(tokens, emb, x);

    const long long DD = (long long)D * D;

    for (int l = 0; l < L; l++) {
        const float* Wql = Wq + (long long)l * H * DD;
        const float* Wkl = Wk + (long long)l * H * DD;
        const float* Wvl = Wv + (long long)l * H * DD;
        const float* bql = bq + (long long)l * H * D;
        const float* bkl = bk + (long long)l * H * D;
        const float* bvl = bv + (long long)l * H * D;

        // 2. Q/K/V projections: per (b,h) GEMM [T,D] = x_b[T,D] @ W_h[D,D] + b_h
        dim3 gqkv(D / BN, T / BM, B * H);
        gemm_k<false, false, true><<<gqkv, 256>>>(
            x, Wql, bql, q, T, D, D, D,
            (long long)T * D, 0, 0, DD,
            (long long)H * T * D, (long long)T * D, D, H);
        gemm_k<false, false, true><<<gqkv, 256>>>(
            x, Wkl, bkl, k, T, D, D, D,
            (long long)T * D, 0, 0, DD,
            (long long)H * T * D, (long long)T * D, D, H);
        gemm_k<false, false, true><<<gqkv, 256>>>(
            x, Wvl, bvl, v, T, D, D, D,
            (long long)T * D, 0, 0, DD,
            (long long)H * T * D, (long long)T * D, D, H);

        // 3. scores = Q @ K^T   [T,T] per (b,h)
        dim3 gsc(T / BN, T / BM, B * H);
        gemm_k<true, false, false><<<gsc, 256>>>(
            q, k, nullptr, sc, T, T, D, T,
            (long long)T * D, 0, (long long)T * D, 0,
            (long long)T * T, 0, 0, 1);

        // 4. causal softmax (no scaling)
        softmax_k<<<B * H * T, 256>>>(sc);

        // 5. O = P @ V, written directly into concat layout [B,T,H*D]
        dim3 go(D / BN, T / BM, B * H);
        gemm_k<false, false, false><<<go, 256>>>(
            sc, v, nullptr, oc, T, D, T, HD,
            (long long)H * T * T, (long long)T * T,
            (long long)H * T * D, (long long)T * D,
            (long long)T * HD, D, 0, H);

        // 6. attn out projection: [NT,D] = oc[NT,HD] @ Wo_l[HD,D] + bo_l
        dim3 gwo(D / BN, NT / BM, 1);
        gemm_k<false, false, true><<<gwo, 256>>>(
            oc, Wo + (long long)l * HD * D, bo + (long long)l * D, t2,
            NT, D, HD, D, 0, 0, 0, 0, 0, 0, 0, 1);

        // 7. x = LN(x + attn)
        addln_k<<<NT, 256>>>(x, t2, ln1g + (long long)l * D, ln1b + (long long)l * D, x);

        // 8. FFN: h1 = relu(x @ W1 + b1)
        dim3 gf1(DFF / BN, NT / BM, 1);
        gemm_k<false, true, true><<<gf1, 256>>>(
            x, W1 + (long long)l * D * DFF, b1 + (long long)l * DFF, h1,
            NT, DFF, D, DFF, 0, 0, 0, 0, 0, 0, 0, 1);

        // 9. f = h1 @ W2 + b2
        dim3 gf2(D / BN, NT / BM, 1);
        gemm_k<false, false, true><<<gf2, 256>>>(
            h1, W2 + (long long)l * DFF * D, b2 + (long long)l * D, t2,
            NT, D, DFF, D, 0, 0, 0, 0, 0, 0, 0, 1);

        // 10. x = LN(x + f)
        addln_k<<<NT, 256>>>(x, t2, ln2g + (long long)l * D, ln2b + (long long)l * D, x);
    }

    // 11. final LN (no residual add)
    addln_k<<<NT, 256>>>(x, nullptr, lnfg, lnfb, xf);

    // 12. logits = xf @ Wout + bout   [NT,V]
    dim3 glg(V / BN, NT / BM, 1);
    gemm_k<false, false, true><<<glg, 256>>>(
        xf, Wout, bout, logits, NT, V, D, V, 0, 0, 0, 0, 0, 0, 0, 1);

    // 13. loss
    lossrow_k<<<NT, V>>>(logits, labels, rowloss);
    lossred_k<<<1, 1024>>>(rowloss, loss);

    // 14. write flattened (logits, loss)
    writeout_k<<<(out_size + 255) / 256, 256>>>(logits, loss, (float*)d_out, out_size);
}

// round 3
// speedup vs baseline: 1.9502x; 1.9502x over previous
#include <cuda_runtime.h>
#include <math.h>
#include <stdint.h>

// ---------------------------------------------------------------------------
// Problem constants (B,T,D,H,L,V = 4,1024,512,8,6,128 ; DFF = 2048)
// ---------------------------------------------------------------------------
namespace cfg {
constexpr int B = 4, T = 1024, D = 512, H = 8, L = 6, V = 128, DFF = 2048;
constexpr int NT = B * T;     // 4096 token rows
constexpr int HD = H * D;     // 4096 concat width
}
using namespace cfg;

// ---------------------------------------------------------------------------
// Static device scratch (no dynamic allocation allowed)
// ---------------------------------------------------------------------------
__device__ float g_x[NT * D];
__device__ float g_q[B * H * T * D];
__device__ float g_k[B * H * T * D];
__device__ float g_v[B * H * T * D];
__device__ float g_sc[(long long)B * H * T * T];
__device__ float g_oc[NT * HD];
__device__ float g_h1[NT * DFF];
__device__ float g_t2[NT * D];
__device__ float g_xf[NT * D];
__device__ float g_logits[NT * V];
__device__ float g_rowloss[NT];
__device__ float g_loss[1];

// ---------------------------------------------------------------------------
// Split-precision bf16 tensor-core GEMM (3x mma.m16n8k16 per fp32 product:
// hi*hi + hi*lo + lo*hi, fp32 accumulate) + cp.async double buffering.
// C[M,N] = A[M,K] @ B (+bias)(+relu), optional B given as [N,K] (TRANSB).
// Block tile 128x128, BK=32, 8 warps of 64x32. All M,N used are multiples of
// 128 and K multiples of 32 -> no bounds checks.
// ---------------------------------------------------------------------------
constexpr int BM = 128, BN = 128, BK = 32;
constexpr int A_FLOATS = BM * BK;            // swizzled [m][32]
constexpr int B_FLOATS = BK * (BN + 8);      // non-trans layout (larger of the two)
constexpr int STAGE_FLOATS = A_FLOATS + B_FLOATS;
constexpr int SMEM_BYTES = 2 * STAGE_FLOATS * 4;    // 67584

__device__ __forceinline__ void cp_async16(uint32_t s, const void* g) {
    asm volatile("cp.async.cg.shared.global [%0], [%1], 16;\n" :: "r"(s), "l"(g));
}
__device__ __forceinline__ void cp_commit() {
    asm volatile("cp.async.commit_group;\n" ::: "memory");
}
template <int N>
__device__ __forceinline__ void cp_wait() {
    asm volatile("cp.async.wait_group %0;\n" :: "n"(N) : "memory");
}

// Split two fp32 into packed bf16x2 (hi) + packed bf16x2 (lo residual).
// Register convention: low 16 bits = first (lower-k) element.
__device__ __forceinline__ void split2(float x0, float x1, uint32_t& hi, uint32_t& lo) {
    uint32_t h;
    asm("cvt.rn.bf16x2.f32 %0, %2, %1;" : "=r"(h) : "f"(x0), "f"(x1));
    float f0, f1;
    asm("{\n\t.reg .b16 a, b;\n\t"
        "mov.b32 {a, b}, %2;\n\t"
        "cvt.f32.bf16 %0, a;\n\t"
        "cvt.f32.bf16 %1, b;\n\t}"
        : "=f"(f0), "=f"(f1) : "r"(h));
    float r0 = x0 - f0, r1 = x1 - f1;
    uint32_t l;
    asm("cvt.rn.bf16x2.f32 %0, %2, %1;" : "=r"(l) : "f"(r0), "f"(r1));
    hi = h; lo = l;
}

__device__ __forceinline__ void mma16(float* c, const uint32_t* a, const uint32_t* b) {
    asm volatile(
        "mma.sync.aligned.m16n8k16.row.col.f32.bf16.bf16.f32 "
        "{%0,%1,%2,%3},{%4,%5,%6,%7},{%8,%9},{%0,%1,%2,%3};"
        : "+f"(c[0]), "+f"(c[1]), "+f"(c[2]), "+f"(c[3])
        : "r"(a[0]), "r"(a[1]), "r"(a[2]), "r"(a[3]), "r"(b[0]), "r"(b[1]));
}

// Issue cp.asyncs for one BK tile of A and B into the given stage.
template <bool TRANSB>
__device__ __forceinline__ void load_tiles(
    const float* __restrict__ A, const float* __restrict__ Bm,
    int K, int N, int m0, int n0, int k0,
    uint32_t sA, uint32_t sB, int tid)
{
    // A [M,K] row-major -> As[m][32] with 16B-group XOR swizzle.
#pragma unroll
    for (int it = 0; it < 4; it++) {
        int lin = tid + it * 256;
        int row = lin >> 3, g = lin & 7;
        const float* gp = A + (long long)(m0 + row) * K + k0 + g * 4;
        uint32_t sp = sA + (uint32_t)((row * 32 + ((g ^ (row & 7)) << 2)) * 4);
        cp_async16(sp, gp);
    }
    if (TRANSB) {
#pragma unroll
        for (int it = 0; it < 4; it++) {
            int lin = tid + it * 256;
            int n = lin >> 3, g = lin & 7;
            const float* gp = Bm + (long long)(n0 + n) * K + k0 + g * 4;
            uint32_t sp = sB + (uint32_t)((n * 32 + ((g ^ (n & 7)) << 2)) * 4);
            cp_async16(sp, gp);
        }
    } else {
        // B [K,N] row-major -> Bs[k][n] with row stride BN+8.
#pragma unroll
        for (int it = 0; it < 4; it++) {
            int lin = tid + it * 256;
            int k = lin >> 5, nv = lin & 31;
            const float* gp = Bm + (long long)(k0 + k) * N + n0 + nv * 4;
            uint32_t sp = sB + (uint32_t)((k * (BN + 8) + nv * 4) * 4);
            cp_async16(sp, gp);
        }
    }
}

template <bool TRANSB, bool RELU, bool BIAS>
__global__ __launch_bounds__(256) void gemm_mma(
    const float* __restrict__ A, const float* __restrict__ Bm,
    const float* __restrict__ bias, float* __restrict__ C,
    int M, int N, int K, int ldc,
    long long aO, long long aI, long long bO, long long bI,
    long long cO, long long cI, long long biasI, int innerB)
{
    const int z = blockIdx.z;
    const int outer = z / innerB;
    const int inner = z - outer * innerB;
    A  += outer * aO + inner * aI;
    Bm += outer * bO + inner * bI;
    C  += outer * cO + inner * cI;
    const float* bp = BIAS ? (bias + inner * biasI) : nullptr;

    extern __shared__ float smem[];
    const uint32_t sbase = (uint32_t)__cvta_generic_to_shared(smem);

    const int tid = threadIdx.x;
    const int lane = tid & 31, warp = tid >> 5;
    const int wm = warp >> 2;          // 0..1
    const int wn = warp & 3;           // 0..3
    const int t4 = lane & 3, g8 = lane >> 2;
    const int m0 = blockIdx.y * BM;
    const int n0 = blockIdx.x * BN;

    float acc[16][4];
#pragma unroll
    for (int i = 0; i < 16; i++)
#pragma unroll
        for (int j = 0; j < 4; j++) acc[i][j] = 0.f;

    // prologue: stage 0
    load_tiles<TRANSB>(A, Bm, K, N, m0, n0, 0, sbase, sbase + A_FLOATS * 4, tid);
    cp_commit();

    int stage = 0;
    for (int k0 = 0; k0 < K; k0 += BK) {
        if (k0 + BK < K) {
            uint32_t so = sbase + (stage ^ 1) * (STAGE_FLOATS * 4);
            load_tiles<TRANSB>(A, Bm, K, N, m0, n0, k0 + BK, so, so + A_FLOATS * 4, tid);
            cp_commit();
            cp_wait<1>();
        } else {
            cp_wait<0>();
        }
        __syncthreads();

        const float* As = smem + stage * STAGE_FLOATS;
        const float* Bs = As + A_FLOATS;

        // two k16 chunks per BK=32
#pragma unroll
        for (int c = 0; c < 2; c++) {
            const int o1 = c * 16 + 2 * t4;       // first k-pair offset
            const int g1 = o1 >> 2, w1 = o1 & 3;  // 4-float group / within-group
            const int g2 = g1 + 2;                // +8 k offset, same w

            uint32_t ah[4][4], al[4][4];
#pragma unroll
            for (int mi = 0; mi < 4; mi++) {
                const int rm = wm * 64 + mi * 16 + g8;
                const int r2 = rm + 8;
                float2 p0 = *(const float2*)&As[rm * 32 + ((g1 ^ (rm & 7)) << 2) + w1];
                float2 p1 = *(const float2*)&As[r2 * 32 + ((g1 ^ (r2 & 7)) << 2) + w1];
                float2 p2 = *(const float2*)&As[rm * 32 + ((g2 ^ (rm & 7)) << 2) + w1];
                float2 p3 = *(const float2*)&As[r2 * 32 + ((g2 ^ (r2 & 7)) << 2) + w1];
                split2(p0.x, p0.y, ah[mi][0], al[mi][0]);
                split2(p1.x, p1.y, ah[mi][1], al[mi][1]);
                split2(p2.x, p2.y, ah[mi][2], al[mi][2]);
                split2(p3.x, p3.y, ah[mi][3], al[mi][3]);
            }

#pragma unroll
            for (int ni = 0; ni < 4; ni++) {
                uint32_t bh[2], bl[2];
                if (TRANSB) {
                    const int rn = wn * 32 + ni * 8 + g8;
                    float2 q0 = *(const float2*)&Bs[rn * 32 + ((g1 ^ (rn & 7)) << 2) + w1];
                    float2 q1 = *(const float2*)&Bs[rn * 32 + ((g2 ^ (rn & 7)) << 2) + w1];
                    split2(q0.x, q0.y, bh[0], bl[0]);
                    split2(q1.x, q1.y, bh[1], bl[1]);
                } else {
                    const int col = wn * 32 + ni * 8 + g8;
                    const int kr = c * 16 + 2 * t4;
                    float f0 = Bs[(kr    ) * (BN + 8) + col];
                    float f1 = Bs[(kr + 1) * (BN + 8) + col];
                    float f2 = Bs[(kr + 8) * (BN + 8) + col];
                    float f3 = Bs[(kr + 9) * (BN + 8) + col];
                    split2(f0, f1, bh[0], bl[0]);
                    split2(f2, f3, bh[1], bl[1]);
                }
#pragma unroll
                for (int mi = 0; mi < 4; mi++) {
                    mma16(acc[mi * 4 + ni], ah[mi], bh);
                    mma16(acc[mi * 4 + ni], ah[mi], bl);
                    mma16(acc[mi * 4 + ni], al[mi], bh);
                }
            }
        }
        __syncthreads();
        stage ^= 1;
    }

    // epilogue (same fragment->C mapping as m16n8k8: rows g8/g8+8, cols 2*t4)
#pragma unroll
    for (int mi = 0; mi < 4; mi++) {
#pragma unroll
        for (int ni = 0; ni < 4; ni++) {
            const float* c = acc[mi * 4 + ni];
            int row = m0 + wm * 64 + mi * 16 + g8;
            int col = n0 + wn * 32 + ni * 8 + t4 * 2;
            float b0 = 0.f, b1 = 0.f;
            if (BIAS) { b0 = bp[col]; b1 = bp[col + 1]; }
            float v0 = c[0] + b0, v1 = c[1] + b1;
            float v2 = c[2] + b0, v3 = c[3] + b1;
            if (RELU) {
                v0 = fmaxf(v0, 0.f); v1 = fmaxf(v1, 0.f);
                v2 = fmaxf(v2, 0.f); v3 = fmaxf(v3, 0.f);
            }
            *(float2*)(C + (long long)row * ldc + col) = make_float2(v0, v1);
            *(float2*)(C + (long long)(row + 8) * ldc + col) = make_float2(v2, v3);
        }
    }
}

// ---------------------------------------------------------------------------
// Embedding gather
// ---------------------------------------------------------------------------
__global__ void embed_k(const int* __restrict__ tok, const float* __restrict__ emb,
                        float* __restrict__ x)
{
    int i = blockIdx.x * blockDim.x + threadIdx.x;
    if (i >= NT * D) return;
    int r = i / D;
    int d = i - r * D;
    x[i] = emb[(long long)tok[r] * D + d];
}

// ---------------------------------------------------------------------------
// Causal softmax (no 1/sqrt(d) scaling — faithful to source).
// ---------------------------------------------------------------------------
__global__ void softmax_k(float* __restrict__ sc)
{
    const long long r = blockIdx.x;
    const int t = (int)(r & (T - 1));
    float* row = sc + r * T;
    const int len = t + 1;
    __shared__ float buf[T];
    __shared__ float red[256];
    const int tid = threadIdx.x;

    float m = -1e30f;
    for (int s = tid; s < len; s += 256) {
        float v = row[s];
        buf[s] = v;
        m = fmaxf(m, v);
    }
    red[tid] = m;
    __syncthreads();
    for (int o = 128; o; o >>= 1) {
        if (tid < o) red[tid] = fmaxf(red[tid], red[tid + o]);
        __syncthreads();
    }
    m = red[0];
    __syncthreads();

    float sum = 0.f;
    for (int s = tid; s < len; s += 256) {
        float e = expf(buf[s] - m);
        buf[s] = e;
        sum += e;
    }
    red[tid] = sum;
    __syncthreads();
    for (int o = 128; o; o >>= 1) {
        if (tid < o) red[tid] += red[tid + o];
        __syncthreads();
    }
    const float inv = 1.f / red[0];
    for (int s = tid; s < T; s += 256)
        row[s] = (s < len) ? buf[s] * inv : 0.f;
}

// ---------------------------------------------------------------------------
// out = LN(xin + a) * g + b   (a may be null; eps = 1e-5). In-place safe.
// ---------------------------------------------------------------------------
__global__ void addln_k(const float* __restrict__ xin, const float* __restrict__ a,
                        const float* __restrict__ g, const float* __restrict__ b,
                        float* __restrict__ out)
{
    const long long r = blockIdx.x;
    __shared__ float buf[D];
    __shared__ float red[256];
    const int tid = threadIdx.x;

    float s = 0.f;
    for (int d = tid; d < D; d += 256) {
        float v = xin[r * D + d];
        if (a) v += a[r * D + d];
        buf[d] = v;
        s += v;
    }
    red[tid] = s;
    __syncthreads();
    for (int o = 128; o; o >>= 1) {
        if (tid < o) red[tid] += red[tid + o];
        __syncthreads();
    }
    const float mean = red[0] * (1.f / D);
    __syncthreads();

    float vs = 0.f;
    for (int d = tid; d < D; d += 256) {
        float dv = buf[d] - mean;
        vs += dv * dv;
    }
    red[tid] = vs;
    __syncthreads();
    for (int o = 128; o; o >>= 1) {
        if (tid < o) red[tid] += red[tid + o];
        __syncthreads();
    }
    const float rstd = rsqrtf(red[0] * (1.f / D) + 1e-5f);
    for (int d = tid; d < D; d += 256)
        out[r * D + d] = (buf[d] - mean) * rstd * g[d] + b[d];
}

// ---------------------------------------------------------------------------
// Cross-entropy
// ---------------------------------------------------------------------------
__global__ void lossrow_k(const float* __restrict__ logits, const int* __restrict__ labels,
                          float* __restrict__ rowloss)
{
    const int r = blockIdx.x;
    const int tid = threadIdx.x;   // V = 128 threads
    __shared__ float red[V];
    const float v = logits[(long long)r * V + tid];
    red[tid] = v;
    __syncthreads();
    for (int o = 64; o; o >>= 1) {
        if (tid < o) red[tid] = fmaxf(red[tid], red[tid + o]);
        __syncthreads();
    }
    const float m = red[0];
    __syncthreads();
    red[tid] = expf(v - m);
    __syncthreads();
    for (int o = 64; o; o >>= 1) {
        if (tid < o) red[tid] += red[tid + o];
        __syncthreads();
    }
    if (tid == 0) {
        int lab = labels[r];
        rowloss[r] = -(logits[(long long)r * V + lab] - m - logf(red[0]));
    }
}

__global__ void lossred_k(const float* __restrict__ rowloss, float* __restrict__ loss)
{
    __shared__ float red[1024];
    const int tid = threadIdx.x;
    float s = 0.f;
    for (int i = tid; i < NT; i += 1024) s += rowloss[i];
    red[tid] = s;
    __syncthreads();
    for (int o = 512; o; o >>= 1) {
        if (tid < o) red[tid] += red[tid + o];
        __syncthreads();
    }
    if (tid == 0) loss[0] = red[0] / (float)NT;
}

__global__ void writeout_k(const float* __restrict__ logits, const float* __restrict__ loss,
                           float* __restrict__ out, int out_size)
{
    int i = blockIdx.x * blockDim.x + threadIdx.x;
    if (i >= out_size) return;
    const int NL = NT * V;
    if (out_size >= NL) out[i] = (i < NL) ? logits[i] : loss[0];
    else out[i] = loss[0];
}

// ---------------------------------------------------------------------------
// Host orchestration
// ---------------------------------------------------------------------------
extern "C" void kernel_launch(void* const* d_in, const int* in_sizes, int n_in,
                              void* d_out, int out_size)
{
    const int*   tokens = (const int*)d_in[0];
    const int*   labels = (const int*)d_in[1];
    const float* emb    = (const float*)d_in[2];
    const float* Wq     = (const float*)d_in[3];
    const float* bq     = (const float*)d_in[4];
    const float* Wk     = (const float*)d_in[5];
    const float* bk     = (const float*)d_in[6];
    const float* Wv     = (const float*)d_in[7];
    const float* bv     = (const float*)d_in[8];
    const float* Wo     = (const float*)d_in[9];
    const float* bo     = (const float*)d_in[10];
    const float* ln1g   = (const float*)d_in[11];
    const float* ln1b   = (const float*)d_in[12];
    const float* W1     = (const float*)d_in[13];
    const float* b1     = (const float*)d_in[14];
    const float* W2     = (const float*)d_in[15];
    const float* b2     = (const float*)d_in[16];
    const float* ln2g   = (const float*)d_in[17];
    const float* ln2b   = (const float*)d_in[18];
    const float* lnfg   = (const float*)d_in[19];
    const float* lnfb   = (const float*)d_in[20];
    const float* Wout   = (const float*)d_in[21];
    const float* bout   = (const float*)d_in[22];

    float *x, *q, *k, *v, *sc, *oc, *h1, *t2, *xf, *logits, *rowloss, *loss;
    cudaGetSymbolAddress((void**)&x, g_x);
    cudaGetSymbolAddress((void**)&q, g_q);
    cudaGetSymbolAddress((void**)&k, g_k);
    cudaGetSymbolAddress((void**)&v, g_v);
    cudaGetSymbolAddress((void**)&sc, g_sc);
    cudaGetSymbolAddress((void**)&oc, g_oc);
    cudaGetSymbolAddress((void**)&h1, g_h1);
    cudaGetSymbolAddress((void**)&t2, g_t2);
    cudaGetSymbolAddress((void**)&xf, g_xf);
    cudaGetSymbolAddress((void**)&logits, g_logits);
    cudaGetSymbolAddress((void**)&rowloss, g_rowloss);
    cudaGetSymbolAddress((void**)&loss, g_loss);

    cudaFuncSetAttribute(gemm_mma<false, false, true>,
                         cudaFuncAttributeMaxDynamicSharedMemorySize, SMEM_BYTES);
    cudaFuncSetAttribute(gemm_mma<true, false, false>,
                         cudaFuncAttributeMaxDynamicSharedMemorySize, SMEM_BYTES);
    cudaFuncSetAttribute(gemm_mma<false, false, false>,
                         cudaFuncAttributeMaxDynamicSharedMemorySize, SMEM_BYTES);
    cudaFuncSetAttribute(gemm_mma<false, true, true>,
                         cudaFuncAttributeMaxDynamicSharedMemorySize, SMEM_BYTES);

    // 1. embedding gather
    embed_k<<<(NT * D + 255) / 256, 256>>>(tokens, emb, x);

    const long long DD = (long long)D * D;

    for (int l = 0; l < L; l++) {
        const float* Wql = Wq + (long long)l * H * DD;
        const float* Wkl = Wk + (long long)l * H * DD;
        const float* Wvl = Wv + (long long)l * H * DD;
        const float* bql = bq + (long long)l * H * D;
        const float* bkl = bk + (long long)l * H * D;
        const float* bvl = bv + (long long)l * H * D;

        // 2. Q/K/V projections: per (b,h) GEMM [T,D] = x_b[T,D] @ W_h[D,D] + b_h
        dim3 gqkv(D / BN, T / BM, B * H);
        gemm_mma<false, false, true><<<gqkv, 256, SMEM_BYTES>>>(
            x, Wql, bql, q, T, D, D, D,
            (long long)T * D, 0, 0, DD,
            (long long)H * T * D, (long long)T * D, D, H);
        gemm_mma<false, false, true><<<gqkv, 256, SMEM_BYTES>>>(
            x, Wkl, bkl, k, T, D, D, D,
            (long long)T * D, 0, 0, DD,
            (long long)H * T * D, (long long)T * D, D, H);
        gemm_mma<false, false, true><<<gqkv, 256, SMEM_BYTES>>>(
            x, Wvl, bvl, v, T, D, D, D,
            (long long)T * D, 0, 0, DD,
            (long long)H * T * D, (long long)T * D, D, H);

        // 3. scores = Q @ K^T   [T,T] per (b,h)
        dim3 gsc(T / BN, T / BM, B * H);
        gemm_mma<true, false, false><<<gsc, 256, SMEM_BYTES>>>(
            q, k, nullptr, sc, T, T, D, T,
            (long long)T * D, 0, (long long)T * D, 0,
            (long long)T * T, 0, 0, 1);

        // 4. causal softmax (no scaling)
        softmax_k<<<B * H * T, 256>>>(sc);

        // 5. O = P @ V, written directly into concat layout [B,T,H*D]
        dim3 go(D / BN, T / BM, B * H);
        gemm_mma<false, false, false><<<go, 256, SMEM_BYTES>>>(
            sc, v, nullptr, oc, T, D, T, HD,
            (long long)H * T * T, (long long)T * T,
            (long long)H * T * D, (long long)T * D,
            (long long)T * HD, D, 0, H);

        // 6. attn out projection
        dim3 gwo(D / BN, NT / BM, 1);
        gemm_mma<false, false, true><<<gwo, 256, SMEM_BYTES>>>(
            oc, Wo + (long long)l * HD * D, bo + (long long)l * D, t2,
            NT, D, HD, D, 0, 0, 0, 0, 0, 0, 0, 1);

        // 7. x = LN(x + attn)
        addln_k<<<NT, 256>>>(x, t2, ln1g + (long long)l * D, ln1b + (long long)l * D, x);

        // 8. FFN1 (+relu)
        dim3 gf1(DFF / BN, NT / BM, 1);
        gemm_mma<false, true, true><<<gf1, 256, SMEM_BYTES>>>(
            x, W1 + (long long)l * D * DFF, b1 + (long long)l * DFF, h1,
            NT, DFF, D, DFF, 0, 0, 0, 0, 0, 0, 0, 1);

        // 9. FFN2
        dim3 gf2(D / BN, NT / BM, 1);
        gemm_mma<false, false, true><<<gf2, 256, SMEM_BYTES>>>(
            h1, W2 + (long long)l * DFF * D, b2 + (long long)l * D, t2,
            NT, D, DFF, D, 0, 0, 0, 0, 0, 0, 0, 1);

        // 10. x = LN(x + f)
        addln_k<<<NT, 256>>>(x, t2, ln2g + (long long)l * D, ln2b + (long long)l * D, x);
    }

    // 11. final LN
    addln_k<<<NT, 256>>>(x, nullptr, lnfg, lnfb, xf);

    // 12. logits
    dim3 glg(V / BN, NT / BM, 1);
    gemm_mma<false, false, true><<<glg, 256, SMEM_BYTES>>>(
        xf, Wout, bout, logits, NT, V, D, V, 0, 0, 0, 0, 0, 0, 0, 1);

    // 13. loss
    lossrow_k<<<NT, V>>>(logits, labels, rowloss);
    lossred_k<<<1, 1024>>>(rowloss, loss);

    // 14. output
    writeout_k<<<(out_size + 255) / 256, 256>>>(logits, loss, (float*)d_out, out_size);
}

// round 4
// speedup vs baseline: 2.1121x; 1.0830x over previous
#include <cuda_runtime.h>
#include <cuda_bf16.h>
#include <math.h>
#include <stdint.h>

// ---------------------------------------------------------------------------
// Problem constants (B,T,D,H,L,V = 4,1024,512,8,6,128 ; DFF = 2048)
// ---------------------------------------------------------------------------
namespace cfg {
constexpr int B = 4, T = 1024, D = 512, H = 8, L = 6, V = 128, DFF = 2048;
constexpr int NT = B * T;
constexpr int HD = H * D;
}
using namespace cfg;

typedef __nv_bfloat16 bf16;

// ---------------------------------------------------------------------------
// Static device scratch
// ---------------------------------------------------------------------------
__device__ float g_x[NT * D];                    // residual stream (fp32)
__device__ float g_sc[(long long)B * H * T * T]; // attention scores (fp32)
__device__ float g_t2[NT * D];                   // sublayer output (fp32)
__device__ float g_logits[NT * V];
__device__ float g_rowloss[NT];
__device__ float g_loss[1];

// bf16 hi/lo activation planes
__device__ __align__(16) bf16 g_xh[NT * D],  g_xl[NT * D];
__device__ __align__(16) bf16 g_qh[B*H*T*D], g_ql[B*H*T*D];
__device__ __align__(16) bf16 g_kh[B*H*T*D], g_kl[B*H*T*D];
__device__ __align__(16) bf16 g_vh[B*H*T*D], g_vl[B*H*T*D];
__device__ __align__(16) bf16 g_ph[(long long)B*H*T*T], g_pl[(long long)B*H*T*T];
__device__ __align__(16) bf16 g_och[NT*HD],  g_ocl[NT*HD];
__device__ __align__(16) bf16 g_h1h[NT*DFF], g_h1l[NT*DFF];
__device__ __align__(16) bf16 g_xfh[NT*D],   g_xfl[NT*D];

// bf16 hi/lo weight planes
constexpr long long WQKV = (long long)L * H * D * D;   // 12.58M
constexpr long long WWO  = (long long)L * HD * D;      // 12.58M
constexpr long long WW1  = (long long)L * D * DFF;     // 6.29M
constexpr long long WW2  = (long long)L * DFF * D;
constexpr long long WOUT = (long long)D * V;
__device__ __align__(16) bf16 g_wqh[WQKV], g_wql[WQKV];
__device__ __align__(16) bf16 g_wkh[WQKV], g_wkl[WQKV];
__device__ __align__(16) bf16 g_wvh[WQKV], g_wvl[WQKV];
__device__ __align__(16) bf16 g_woh[WWO],  g_wol[WWO];
__device__ __align__(16) bf16 g_w1h[WW1],  g_w1l[WW1];
__device__ __align__(16) bf16 g_w2h[WW2],  g_w2l[WW2];
__device__ __align__(16) bf16 g_wouth[WOUT], g_woutl[WOUT];

// ---------------------------------------------------------------------------
// Small PTX helpers
// ---------------------------------------------------------------------------
__device__ __forceinline__ void cp_async16(uint32_t s, const void* g) {
    asm volatile("cp.async.cg.shared.global [%0], [%1], 16;\n" :: "r"(s), "l"(g));
}
__device__ __forceinline__ void cp_commit() {
    asm volatile("cp.async.commit_group;\n" ::: "memory");
}
template <int N>
__device__ __forceinline__ void cp_wait() {
    asm volatile("cp.async.wait_group %0;\n" :: "n"(N) : "memory");
}
// pack two fp32 -> bf16x2 hi plane + bf16x2 residual plane (low half = first elem)
__device__ __forceinline__ void split2(float x0, float x1, uint32_t& hi, uint32_t& lo) {
    uint32_t h;
    asm("cvt.rn.bf16x2.f32 %0, %2, %1;" : "=r"(h) : "f"(x0), "f"(x1));
    float f0, f1;
    asm("{\n\t.reg .b16 a, b;\n\t"
        "mov.b32 {a, b}, %2;\n\t"
        "cvt.f32.bf16 %0, a;\n\t"
        "cvt.f32.bf16 %1, b;\n\t}"
        : "=f"(f0), "=f"(f1) : "r"(h));
    float r0 = x0 - f0, r1 = x1 - f1;
    uint32_t l;
    asm("cvt.rn.bf16x2.f32 %0, %2, %1;" : "=r"(l) : "f"(r0), "f"(r1));
    hi = h; lo = l;
}
__device__ __forceinline__ void mma16(float* c, const uint32_t* a, const uint32_t* b) {
    asm volatile(
        "mma.sync.aligned.m16n8k16.row.col.f32.bf16.bf16.f32 "
        "{%0,%1,%2,%3},{%4,%5,%6,%7},{%8,%9},{%0,%1,%2,%3};"
        : "+f"(c[0]), "+f"(c[1]), "+f"(c[2]), "+f"(c[3])
        : "r"(a[0]), "r"(a[1]), "r"(a[2]), "r"(a[3]), "r"(b[0]), "r"(b[1]));
}
__device__ __forceinline__ void ldsm_x4(uint32_t* r, uint32_t a) {
    asm volatile("ldmatrix.sync.aligned.m8n8.x4.shared.b16 {%0,%1,%2,%3}, [%4];"
        : "=r"(r[0]), "=r"(r[1]), "=r"(r[2]), "=r"(r[3]) : "r"(a));
}
__device__ __forceinline__ void ldsm_x2(uint32_t* r, uint32_t a) {
    asm volatile("ldmatrix.sync.aligned.m8n8.x2.shared.b16 {%0,%1}, [%2];"
        : "=r"(r[0]), "=r"(r[1]) : "r"(a));
}
__device__ __forceinline__ void ldsm_x2t(uint32_t* r, uint32_t a) {
    asm volatile("ldmatrix.sync.aligned.m8n8.x2.trans.shared.b16 {%0,%1}, [%2];"
        : "=r"(r[0]), "=r"(r[1]) : "r"(a));
}

// ---------------------------------------------------------------------------
// bf16 split-precision GEMM: C = Ah@Bh + Ah@Bl + Al@Bh  (fp32 accum)
// Block 128x128, BK=32, 8 warps (2x4) of 64x32, cp.async double buffer,
// ldmatrix fragment loads. All M,N mult of 128, K mult of 32.
// ---------------------------------------------------------------------------
constexpr int BM = 128, BN = 128, BK = 32;
// smem byte offsets within a stage (each plane tile = 8 KB)
constexpr uint32_t OFF_AH = 0, OFF_AL = 8192, OFF_BH = 16384, OFF_BL = 24576;
constexpr uint32_t STAGE_BYTES = 32768;
constexpr uint32_t SMEM_BYTES = 2 * STAGE_BYTES;   // 64 KB

// A-style tile [128 rows][32 bf16]: two rows per 128B line, XOR swizzle.
__device__ __forceinline__ uint32_t pa_off(int m, int g) {
    int line = m >> 1;
    int q = ((m & 1) << 2) | g;
    return (uint32_t)((line << 7) + ((q ^ (line & 7)) << 4));
}
// B [K,N] tile [32 k][128 bf16]: two 128B lines per k row, XOR swizzle by k.
__device__ __forceinline__ uint32_t pb_off(int k, int ng) {
    int line = (k << 1) | (ng >> 3);
    int q = ng & 7;
    return (uint32_t)((line << 7) + ((q ^ (k & 7)) << 4));
}

template <bool TRANSB>
__device__ __forceinline__ void load_tiles(
    const bf16* __restrict__ Ah, const bf16* __restrict__ Al,
    const bf16* __restrict__ Bh, const bf16* __restrict__ Bl,
    int K, int N, int m0, int n0, int k0, uint32_t sbase, int tid)
{
    {   // A planes: thread -> row m, two 16B granules
        int m = tid & 127;
        int gb = (tid >> 7) << 1;
#pragma unroll
        for (int it = 0; it < 2; it++) {
            int g = gb + it;
            long long go = (long long)(m0 + m) * K + k0 + g * 8;
            uint32_t po = pa_off(m, g);
            cp_async16(sbase + OFF_AH + po, Ah + go);
            cp_async16(sbase + OFF_AL + po, Al + go);
        }
    }
    if (TRANSB) {   // B stored [N,K]: same tile shape as A
        int n = tid & 127;
        int gb = (tid >> 7) << 1;
#pragma unroll
        for (int it = 0; it < 2; it++) {
            int g = gb + it;
            long long go = (long long)(n0 + n) * K + k0 + g * 8;
            uint32_t po = pa_off(n, g);
            cp_async16(sbase + OFF_BH + po, Bh + go);
            cp_async16(sbase + OFF_BL + po, Bl + go);
        }
    } else {        // B stored [K,N]
        int k = tid >> 3;
        int gb = (tid & 7) << 1;
#pragma unroll
        for (int it = 0; it < 2; it++) {
            int g = gb + it;
            long long go = (long long)(k0 + k) * N + n0 + g * 8;
            uint32_t po = pb_off(k, g);
            cp_async16(sbase + OFF_BH + po, Bh + go);
            cp_async16(sbase + OFF_BL + po, Bl + go);
        }
    }
}

template <bool TRANSB, bool RELU, bool BIAS, bool SPLIT_OUT>
__global__ __launch_bounds__(256, 2) void gemm_bf3(
    const bf16* __restrict__ Ah, const bf16* __restrict__ Al,
    const bf16* __restrict__ Bh, const bf16* __restrict__ Bl,
    const float* __restrict__ bias,
    float* __restrict__ C, bf16* __restrict__ Ch, bf16* __restrict__ Cl,
    int M, int N, int K, int ldc,
    long long aO, long long aI, long long bO, long long bI,
    long long cO, long long cI, long long biasI, int innerB)
{
    const int z = blockIdx.z;
    const int outer = z / innerB;
    const int inner = z - outer * innerB;
    const long long ao = outer * aO + inner * aI;
    const long long bo = outer * bO + inner * bI;
    const long long co = outer * cO + inner * cI;
    Ah += ao; Al += ao;
    Bh += bo; Bl += bo;
    if (SPLIT_OUT) { Ch += co; Cl += co; } else { C += co; }
    const float* bp = BIAS ? (bias + inner * biasI) : nullptr;

    extern __shared__ char smem[];
    const uint32_t sbase = (uint32_t)__cvta_generic_to_shared(smem);

    const int tid = threadIdx.x;
    const int lane = tid & 31, warp = tid >> 5;
    const int wm = warp >> 2;
    const int wn = warp & 3;
    const int t4 = lane & 3, g8 = lane >> 2;
    const int m0 = blockIdx.y * BM;
    const int n0 = blockIdx.x * BN;

    // per-lane ldmatrix address components
    const int rowA = lane & 15;          // row within 16-row fragment
    const int kSelA = lane >> 4;         // 0/1 -> k granule within chunk
    const int lsel = lane & 15;          // x2 address lanes

    float acc[16][4];
#pragma unroll
    for (int i = 0; i < 16; i++)
#pragma unroll
        for (int j = 0; j < 4; j++) acc[i][j] = 0.f;

    load_tiles<TRANSB>(Ah, Al, Bh, Bl, K, N, m0, n0, 0, sbase, tid);
    cp_commit();

    int stage = 0;
    for (int k0 = 0; k0 < K; k0 += BK) {
        if (k0 + BK < K) {
            load_tiles<TRANSB>(Ah, Al, Bh, Bl, K, N, m0, n0, k0 + BK,
                               sbase + (stage ^ 1) * STAGE_BYTES, tid);
            cp_commit();
            cp_wait<1>();
        } else {
            cp_wait<0>();
        }
        __syncthreads();

        const uint32_t sa = sbase + stage * STAGE_BYTES;

#pragma unroll
        for (int c = 0; c < 2; c++) {
            uint32_t ah[4][4], al[4][4];
#pragma unroll
            for (int mi = 0; mi < 4; mi++) {
                int m = wm * 64 + mi * 16 + rowA;
                int g = 2 * c + kSelA;
                uint32_t po = pa_off(m, g);
                ldsm_x4(ah[mi], sa + OFF_AH + po);
                ldsm_x4(al[mi], sa + OFF_AL + po);
            }
#pragma unroll
            for (int ni = 0; ni < 4; ni++) {
                uint32_t bh[2], bl[2];
                if (TRANSB) {
                    int n = wn * 32 + ni * 8 + (lsel & 7);
                    int g = 2 * c + (lsel >> 3);
                    uint32_t po = pa_off(n, g);
                    ldsm_x2(bh, sa + OFF_BH + po);
                    ldsm_x2(bl, sa + OFF_BL + po);
                } else {
                    int k = c * 16 + lsel;
                    int ng = wn * 4 + ni;
                    uint32_t po = pb_off(k, ng);
                    ldsm_x2t(bh, sa + OFF_BH + po);
                    ldsm_x2t(bl, sa + OFF_BL + po);
                }
#pragma unroll
                for (int mi = 0; mi < 4; mi++) {
                    mma16(acc[mi * 4 + ni], ah[mi], bh);
                    mma16(acc[mi * 4 + ni], ah[mi], bl);
                    mma16(acc[mi * 4 + ni], al[mi], bh);
                }
            }
        }
        __syncthreads();
        stage ^= 1;
    }

    // epilogue: fragment (mi,ni): rows g8 / g8+8, cols 2*t4, 2*t4+1
#pragma unroll
    for (int mi = 0; mi < 4; mi++) {
#pragma unroll
        for (int ni = 0; ni < 4; ni++) {
            const float* a = acc[mi * 4 + ni];
            int row = m0 + wm * 64 + mi * 16 + g8;
            int col = n0 + wn * 32 + ni * 8 + t4 * 2;
            float b0 = 0.f, b1 = 0.f;
            if (BIAS) { b0 = bp[col]; b1 = bp[col + 1]; }
            float v0 = a[0] + b0, v1 = a[1] + b1;
            float v2 = a[2] + b0, v3 = a[3] + b1;
            if (RELU) {
                v0 = fmaxf(v0, 0.f); v1 = fmaxf(v1, 0.f);
                v2 = fmaxf(v2, 0.f); v3 = fmaxf(v3, 0.f);
            }
            if (SPLIT_OUT) {
                uint32_t h0, l0, h1, l1;
                split2(v0, v1, h0, l0);
                split2(v2, v3, h1, l1);
                *(uint32_t*)(Ch + (long long)row * ldc + col) = h0;
                *(uint32_t*)(Cl + (long long)row * ldc + col) = l0;
                *(uint32_t*)(Ch + (long long)(row + 8) * ldc + col) = h1;
                *(uint32_t*)(Cl + (long long)(row + 8) * ldc + col) = l1;
            } else {
                *(float2*)(C + (long long)row * ldc + col) = make_float2(v0, v1);
                *(float2*)(C + (long long)(row + 8) * ldc + col) = make_float2(v2, v3);
            }
        }
    }
}

// ---------------------------------------------------------------------------
// Elementwise fp32 -> bf16 hi/lo split (for weights), vectorized x4.
// ---------------------------------------------------------------------------
__global__ void split_arr(const float4* __restrict__ src,
                          uint32_t* __restrict__ hi, uint32_t* __restrict__ lo,
                          long long n4)
{
    long long i = (long long)blockIdx.x * blockDim.x + threadIdx.x;
    if (i >= n4) return;
    float4 v = src[i];
    uint32_t h0, l0, h1, l1;
    split2(v.x, v.y, h0, l0);
    split2(v.z, v.w, h1, l1);
    hi[2 * i] = h0; hi[2 * i + 1] = h1;
    lo[2 * i] = l0; lo[2 * i + 1] = l1;
}

// ---------------------------------------------------------------------------
// Embedding gather: fp32 x + bf16 hi/lo planes
// ---------------------------------------------------------------------------
__global__ void embed_k(const int* __restrict__ tok, const float* __restrict__ emb,
                        float* __restrict__ x, bf16* __restrict__ xh, bf16* __restrict__ xl)
{
    int i = blockIdx.x * blockDim.x + threadIdx.x;
    if (i >= NT * D) return;
    int r = i / D;
    int d = i - r * D;
    float v = emb[(long long)tok[r] * D + d];
    x[i] = v;
    bf16 h = __float2bfloat16_rn(v);
    xh[i] = h;
    xl[i] = __float2bfloat16_rn(v - __bfloat162float(h));
}

// ---------------------------------------------------------------------------
// Causal softmax (no 1/sqrt(d) scaling). Reads fp32 scores, writes bf16 hi/lo P.
// ---------------------------------------------------------------------------
__global__ void softmax_k(const float* __restrict__ sc,
                          bf16* __restrict__ ph, bf16* __restrict__ pl)
{
    const long long r = blockIdx.x;
    const int t = (int)(r & (T - 1));
    const float* row = sc + r * T;
    const int len = t + 1;
    __shared__ float buf[T];
    __shared__ float red[256];
    const int tid = threadIdx.x;

    float m = -1e30f;
    for (int s = tid; s < len; s += 256) {
        float v = row[s];
        buf[s] = v;
        m = fmaxf(m, v);
    }
    red[tid] = m;
    __syncthreads();
    for (int o = 128; o; o >>= 1) {
        if (tid < o) red[tid] = fmaxf(red[tid], red[tid + o]);
        __syncthreads();
    }
    m = red[0];
    __syncthreads();

    float sum = 0.f;
    for (int s = tid; s < len; s += 256) {
        float e = expf(buf[s] - m);
        buf[s] = e;
        sum += e;
    }
    red[tid] = sum;
    __syncthreads();
    for (int o = 128; o; o >>= 1) {
        if (tid < o) red[tid] += red[tid + o];
        __syncthreads();
    }
    const float inv = 1.f / red[0];
    bf16 zero = __float2bfloat16_rn(0.f);
    for (int s = tid; s < T; s += 256) {
        if (s < len) {
            float v = buf[s] * inv;
            bf16 h = __float2bfloat16_rn(v);
            ph[r * T + s] = h;
            pl[r * T + s] = __float2bfloat16_rn(v - __bfloat162float(h));
        } else {
            ph[r * T + s] = zero;
            pl[r * T + s] = zero;
        }
    }
}

// ---------------------------------------------------------------------------
// out = LN(xin + a) * g + b; writes fp32 out + optional bf16 hi/lo planes.
// ---------------------------------------------------------------------------
__global__ void addln_k(const float* __restrict__ xin, const float* __restrict__ a,
                        const float* __restrict__ g, const float* __restrict__ b,
                        float* __restrict__ out,
                        bf16* __restrict__ oh, bf16* __restrict__ ol)
{
    const long long r = blockIdx.x;
    __shared__ float buf[D];
    __shared__ float red[256];
    const int tid = threadIdx.x;

    float s = 0.f;
    for (int d = tid; d < D; d += 256) {
        float v = xin[r * D + d];
        if (a) v += a[r * D + d];
        buf[d] = v;
        s += v;
    }
    red[tid] = s;
    __syncthreads();
    for (int o = 128; o; o >>= 1) {
        if (tid < o) red[tid] += red[tid + o];
        __syncthreads();
    }
    const float mean = red[0] * (1.f / D);
    __syncthreads();

    float vs = 0.f;
    for (int d = tid; d < D; d += 256) {
        float dv = buf[d] - mean;
        vs += dv * dv;
    }
    red[tid] = vs;
    __syncthreads();
    for (int o = 128; o; o >>= 1) {
        if (tid < o) red[tid] += red[tid + o];
        __syncthreads();
    }
    const float rstd = rsqrtf(red[0] * (1.f / D) + 1e-5f);
    for (int d = tid; d < D; d += 256) {
        float v = (buf[d] - mean) * rstd * g[d] + b[d];
        out[r * D + d] = v;
        if (oh) {
            bf16 h = __float2bfloat16_rn(v);
            oh[r * D + d] = h;
            ol[r * D + d] = __float2bfloat16_rn(v - __bfloat162float(h));
        }
    }
}

// ---------------------------------------------------------------------------
// Cross-entropy + output
// ---------------------------------------------------------------------------
__global__ void lossrow_k(const float* __restrict__ logits, const int* __restrict__ labels,
                          float* __restrict__ rowloss)
{
    const int r = blockIdx.x;
    const int tid = threadIdx.x;
    __shared__ float red[V];
    const float v = logits[(long long)r * V + tid];
    red[tid] = v;
    __syncthreads();
    for (int o = 64; o; o >>= 1) {
        if (tid < o) red[tid] = fmaxf(red[tid], red[tid + o]);
        __syncthreads();
    }
    const float m = red[0];
    __syncthreads();
    red[tid] = expf(v - m);
    __syncthreads();
    for (int o = 64; o; o >>= 1) {
        if (tid < o) red[tid] += red[tid + o];
        __syncthreads();
    }
    if (tid == 0) {
        int lab = labels[r];
        rowloss[r] = -(logits[(long long)r * V + lab] - m - logf(red[0]));
    }
}

__global__ void lossred_k(const float* __restrict__ rowloss, float* __restrict__ loss)
{
    __shared__ float red[1024];
    const int tid = threadIdx.x;
    float s = 0.f;
    for (int i = tid; i < NT; i += 1024) s += rowloss[i];
    red[tid] = s;
    __syncthreads();
    for (int o = 512; o; o >>= 1) {
        if (tid < o) red[tid] += red[tid + o];
        __syncthreads();
    }
    if (tid == 0) loss[0] = red[0] / (float)NT;
}

__global__ void writeout_k(const float* __restrict__ logits, const float* __restrict__ loss,
                           float* __restrict__ out, int out_size)
{
    int i = blockIdx.x * blockDim.x + threadIdx.x;
    if (i >= out_size) return;
    const int NL = NT * V;
    if (out_size >= NL) out[i] = (i < NL) ? logits[i] : loss[0];
    else out[i] = loss[0];
}

// ---------------------------------------------------------------------------
// Host orchestration
// ---------------------------------------------------------------------------
static inline void split_launch(const float* src, bf16* hi, bf16* lo, long long n) {
    long long n4 = n / 4;
    split_arr<<<(unsigned)((n4 + 255) / 256), 256>>>(
        (const float4*)src, (uint32_t*)hi, (uint32_t*)lo, n4);
}

extern "C" void kernel_launch(void* const* d_in, const int* in_sizes, int n_in,
                              void* d_out, int out_size)
{
    const int*   tokens = (const int*)d_in[0];
    const int*   labels = (const int*)d_in[1];
    const float* emb    = (const float*)d_in[2];
    const float* Wq     = (const float*)d_in[3];
    const float* bq     = (const float*)d_in[4];
    const float* Wk     = (const float*)d_in[5];
    const float* bk     = (const float*)d_in[6];
    const float* Wv     = (const float*)d_in[7];
    const float* bv     = (const float*)d_in[8];
    const float* Wo     = (const float*)d_in[9];
    const float* bo     = (const float*)d_in[10];
    const float* ln1g   = (const float*)d_in[11];
    const float* ln1b   = (const float*)d_in[12];
    const float* W1     = (const float*)d_in[13];
    const float* b1     = (const float*)d_in[14];
    const float* W2     = (const float*)d_in[15];
    const float* b2     = (const float*)d_in[16];
    const float* ln2g   = (const float*)d_in[17];
    const float* ln2b   = (const float*)d_in[18];
    const float* lnfg   = (const float*)d_in[19];
    const float* lnfb   = (const float*)d_in[20];
    const float* Wout   = (const float*)d_in[21];
    const float* bout   = (const float*)d_in[22];

    float *x, *sc, *t2, *logits, *rowloss, *loss;
    cudaGetSymbolAddress((void**)&x, g_x);
    cudaGetSymbolAddress((void**)&sc, g_sc);
    cudaGetSymbolAddress((void**)&t2, g_t2);
    cudaGetSymbolAddress((void**)&logits, g_logits);
    cudaGetSymbolAddress((void**)&rowloss, g_rowloss);
    cudaGetSymbolAddress((void**)&loss, g_loss);

    bf16 *xh,*xl,*qh,*ql,*kh,*kl,*vh,*vl,*ph,*pl,*och,*ocl,*h1h,*h1l,*xfh,*xfl;
    cudaGetSymbolAddress((void**)&xh, g_xh);   cudaGetSymbolAddress((void**)&xl, g_xl);
    cudaGetSymbolAddress((void**)&qh, g_qh);   cudaGetSymbolAddress((void**)&ql, g_ql);
    cudaGetSymbolAddress((void**)&kh, g_kh);   cudaGetSymbolAddress((void**)&kl, g_kl);
    cudaGetSymbolAddress((void**)&vh, g_vh);   cudaGetSymbolAddress((void**)&vl, g_vl);
    cudaGetSymbolAddress((void**)&ph, g_ph);   cudaGetSymbolAddress((void**)&pl, g_pl);
    cudaGetSymbolAddress((void**)&och, g_och); cudaGetSymbolAddress((void**)&ocl, g_ocl);
    cudaGetSymbolAddress((void**)&h1h, g_h1h); cudaGetSymbolAddress((void**)&h1l, g_h1l);
    cudaGetSymbolAddress((void**)&xfh, g_xfh); cudaGetSymbolAddress((void**)&xfl, g_xfl);

    bf16 *wqh,*wql,*wkh,*wkl,*wvh,*wvl,*woh,*wol,*w1h,*w1l,*w2h,*w2l,*wouth,*woutl;
    cudaGetSymbolAddress((void**)&wqh, g_wqh); cudaGetSymbolAddress((void**)&wql, g_wql);
    cudaGetSymbolAddress((void**)&wkh, g_wkh); cudaGetSymbolAddress((void**)&wkl, g_wkl);
    cudaGetSymbolAddress((void**)&wvh, g_wvh); cudaGetSymbolAddress((void**)&wvl, g_wvl);
    cudaGetSymbolAddress((void**)&woh, g_woh); cudaGetSymbolAddress((void**)&wol, g_wol);
    cudaGetSymbolAddress((void**)&w1h, g_w1h); cudaGetSymbolAddress((void**)&w1l, g_w1l);
    cudaGetSymbolAddress((void**)&w2h, g_w2h); cudaGetSymbolAddress((void**)&w2l, g_w2l);
    cudaGetSymbolAddress((void**)&wouth, g_wouth); cudaGetSymbolAddress((void**)&woutl, g_woutl);

    cudaFuncSetAttribute(gemm_bf3<false,false,true,true>,
                         cudaFuncAttributeMaxDynamicSharedMemorySize, SMEM_BYTES);
    cudaFuncSetAttribute(gemm_bf3<true,false,false,false>,
                         cudaFuncAttributeMaxDynamicSharedMemorySize, SMEM_BYTES);
    cudaFuncSetAttribute(gemm_bf3<false,false,false,true>,
                         cudaFuncAttributeMaxDynamicSharedMemorySize, SMEM_BYTES);
    cudaFuncSetAttribute(gemm_bf3<false,false,true,false>,
                         cudaFuncAttributeMaxDynamicSharedMemorySize, SMEM_BYTES);
    cudaFuncSetAttribute(gemm_bf3<false,true,true,true>,
                         cudaFuncAttributeMaxDynamicSharedMemorySize, SMEM_BYTES);

    // 0. split all weights into bf16 hi/lo planes
    split_launch(Wq, wqh, wql, WQKV);
    split_launch(Wk, wkh, wkl, WQKV);
    split_launch(Wv, wvh, wvl, WQKV);
    split_launch(Wo, woh, wol, WWO);
    split_launch(W1, w1h, w1l, WW1);
    split_launch(W2, w2h, w2l, WW2);
    split_launch(Wout, wouth, woutl, WOUT);

    // 1. embedding gather (+split)
    embed_k<<<(NT * D + 255) / 256, 256>>>(tokens, emb, x, xh, xl);

    const long long DD = (long long)D * D;

    for (int l = 0; l < L; l++) {
        const long long wOff = (long long)l * H * DD;
        const long long bOff = (long long)l * H * D;

        // 2. Q/K/V projections -> split outputs
        dim3 gqkv(D / BN, T / BM, B * H);
        gemm_bf3<false,false,true,true><<<gqkv, 256, SMEM_BYTES>>>(
            xh, xl, wqh + wOff, wql + wOff, bq + bOff,
            nullptr, qh, ql, T, D, D, D,
            (long long)T * D, 0, 0, DD,
            (long long)H * T * D, (long long)T * D, D, H);
        gemm_bf3<false,false,true,true><<<gqkv, 256, SMEM_BYTES>>>(
            xh, xl, wkh + wOff, wkl + wOff, bk + bOff,
            nullptr, kh, kl, T, D, D, D,
            (long long)T * D, 0, 0, DD,
            (long long)H * T * D, (long long)T * D, D, H);
        gemm_bf3<false,false,true,true><<<gqkv, 256, SMEM_BYTES>>>(
            xh, xl, wvh + wOff, wvl + wOff, bv + bOff,
            nullptr, vh, vl, T, D, D, D,
            (long long)T * D, 0, 0, DD,
            (long long)H * T * D, (long long)T * D, D, H);

        // 3. scores = Q @ K^T (fp32 out)
        dim3 gsc(T / BN, T / BM, B * H);
        gemm_bf3<true,false,false,false><<<gsc, 256, SMEM_BYTES>>>(
            qh, ql, kh, kl, nullptr,
            sc, nullptr, nullptr, T, T, D, T,
            (long long)T * D, 0, (long long)T * D, 0,
            (long long)T * T, 0, 0, 1);

        // 4. causal softmax -> split P
        softmax_k<<<B * H * T, 256>>>(sc, ph, pl);

        // 5. O = P @ V -> split oc in concat layout
        dim3 go(D / BN, T / BM, B * H);
        gemm_bf3<false,false,false,true><<<go, 256, SMEM_BYTES>>>(
            ph, pl, vh, vl, nullptr,
            nullptr, och, ocl, T, D, T, HD,
            (long long)H * T * T, (long long)T * T,
            (long long)H * T * D, (long long)T * D,
            (long long)T * HD, D, 0, H);

        // 6. attn out projection (fp32 out)
        dim3 gwo(D / BN, NT / BM, 1);
        gemm_bf3<false,false,true,false><<<gwo, 256, SMEM_BYTES>>>(
            och, ocl, woh + (long long)l * HD * D, wol + (long long)l * HD * D,
            bo + (long long)l * D,
            t2, nullptr, nullptr, NT, D, HD, D, 0, 0, 0, 0, 0, 0, 0, 1);

        // 7. x = LN(x + attn), with split planes for next GEMM
        addln_k<<<NT, 256>>>(x, t2, ln1g + (long long)l * D, ln1b + (long long)l * D,
                             x, xh, xl);

        // 8. FFN1 (+relu) -> split h1
        dim3 gf1(DFF / BN, NT / BM, 1);
        gemm_bf3<false,true,true,true><<<gf1, 256, SMEM_BYTES>>>(
            xh, xl, w1h + (long long)l * D * DFF, w1l + (long long)l * D * DFF,
            b1 + (long long)l * DFF,
            nullptr, h1h, h1l, NT, DFF, D, DFF, 0, 0, 0, 0, 0, 0, 0, 1);

        // 9. FFN2 (fp32 out)
        dim3 gf2(D / BN, NT / BM, 1);
        gemm_bf3<false,false,true,false><<<gf2, 256, SMEM_BYTES>>>(
            h1h, h1l, w2h + (long long)l * DFF * D, w2l + (long long)l * DFF * D,
            b2 + (long long)l * D,
            t2, nullptr, nullptr, NT, D, DFF, D, 0, 0, 0, 0, 0, 0, 0, 1);

        // 10. x = LN(x + f)
        addln_k<<<NT, 256>>>(x, t2, ln2g + (long long)l * D, ln2b + (long long)l * D,
                             x, xh, xl);
    }

    // 11. final LN -> split xf
    addln_k<<<NT, 256>>>(x, nullptr, lnfg, lnfb, t2, xfh, xfl);

    // 12. logits
    dim3 glg(V / BN, NT / BM, 1);
    gemm_bf3<false,false,true,false><<<glg, 256, SMEM_BYTES>>>(
        xfh, xfl, wouth, woutl, bout,
        logits, nullptr, nullptr, NT, V, D, V, 0, 0, 0, 0, 0, 0, 0, 1);

    // 13. loss
    lossrow_k<<<NT, V>>>(logits, labels, rowloss);
    lossred_k<<<1, 1024>>>(rowloss, loss);

    // 14. output
    writeout_k<<<(out_size + 255) / 256, 256>>>(logits, loss, (float*)d_out, out_size);
}

// round 6
// speedup vs baseline: 2.4840x; 1.1761x over previous
#include <cuda_runtime.h>
#include <cuda_bf16.h>
#include <math.h>
#include <stdint.h>

// ---------------------------------------------------------------------------
// Problem constants (B,T,D,H,L,V = 4,1024,512,8,6,128 ; DFF = 2048)
// ---------------------------------------------------------------------------
namespace cfg {
constexpr int B = 4, T = 1024, D = 512, H = 8, L = 6, V = 128, DFF = 2048;
constexpr int NT = B * T;
constexpr int HD = H * D;
}
using namespace cfg;

typedef __nv_bfloat16 bf16;

// ---------------------------------------------------------------------------
// Static device scratch
// ---------------------------------------------------------------------------
__device__ float g_x[NT * D];
__device__ float g_sc[(long long)B * H * T * T];
__device__ float g_t2[NT * D];
__device__ float g_logits[NT * V];
__device__ float g_rowloss[NT];
__device__ float g_loss[1];

__device__ __align__(16) bf16 g_xh[NT * D],  g_xl[NT * D];
__device__ __align__(16) bf16 g_qh[B*H*T*D], g_ql[B*H*T*D];
__device__ __align__(16) bf16 g_kh[B*H*T*D], g_kl[B*H*T*D];
__device__ __align__(16) bf16 g_vh[B*H*T*D], g_vl[B*H*T*D];
__device__ __align__(16) bf16 g_ph[(long long)B*H*T*T], g_pl[(long long)B*H*T*T];
__device__ __align__(16) bf16 g_och[NT*HD],  g_ocl[NT*HD];
__device__ __align__(16) bf16 g_h1h[NT*DFF], g_h1l[NT*DFF];
__device__ __align__(16) bf16 g_xfh[NT*D],   g_xfl[NT*D];

constexpr long long WQKV = (long long)L * H * D * D;
constexpr long long WWO  = (long long)L * HD * D;
constexpr long long WW1  = (long long)L * D * DFF;
constexpr long long WW2  = (long long)L * DFF * D;
constexpr long long WOUT = (long long)D * V;
__device__ __align__(16) bf16 g_wqh[WQKV], g_wql[WQKV];
__device__ __align__(16) bf16 g_wkh[WQKV], g_wkl[WQKV];
__device__ __align__(16) bf16 g_wvh[WQKV], g_wvl[WQKV];
__device__ __align__(16) bf16 g_woh[WWO],  g_wol[WWO];
__device__ __align__(16) bf16 g_w1h[WW1],  g_w1l[WW1];
__device__ __align__(16) bf16 g_w2h[WW2],  g_w2l[WW2];
__device__ __align__(16) bf16 g_wouth[WOUT], g_woutl[WOUT];

// ---------------------------------------------------------------------------
// PTX helpers
// ---------------------------------------------------------------------------
__device__ __forceinline__ void cp_async16(uint32_t s, const void* g) {
    asm volatile("cp.async.cg.shared.global [%0], [%1], 16;\n" :: "r"(s), "l"(g));
}
__device__ __forceinline__ void cp_commit() {
    asm volatile("cp.async.commit_group;\n" ::: "memory");
}
template <int N>
__device__ __forceinline__ void cp_wait() {
    asm volatile("cp.async.wait_group %0;\n" :: "n"(N) : "memory");
}
__device__ __forceinline__ void split2(float x0, float x1, uint32_t& hi, uint32_t& lo) {
    uint32_t h;
    asm("cvt.rn.bf16x2.f32 %0, %2, %1;" : "=r"(h) : "f"(x0), "f"(x1));
    float f0, f1;
    asm("{\n\t.reg .b16 a, b;\n\t"
        "mov.b32 {a, b}, %2;\n\t"
        "cvt.f32.bf16 %0, a;\n\t"
        "cvt.f32.bf16 %1, b;\n\t}"
        : "=f"(f0), "=f"(f1) : "r"(h));
    float r0 = x0 - f0, r1 = x1 - f1;
    uint32_t l;
    asm("cvt.rn.bf16x2.f32 %0, %2, %1;" : "=r"(l) : "f"(r0), "f"(r1));
    hi = h; lo = l;
}
__device__ __forceinline__ void mma16(float* c, const uint32_t* a, const uint32_t* b) {
    asm volatile(
        "mma.sync.aligned.m16n8k16.row.col.f32.bf16.bf16.f32 "
        "{%0,%1,%2,%3},{%4,%5,%6,%7},{%8,%9},{%0,%1,%2,%3};"
        : "+f"(c[0]), "+f"(c[1]), "+f"(c[2]), "+f"(c[3])
        : "r"(a[0]), "r"(a[1]), "r"(a[2]), "r"(a[3]), "r"(b[0]), "r"(b[1]));
}
__device__ __forceinline__ void ldsm_x4(uint32_t* r, uint32_t a) {
    asm volatile("ldmatrix.sync.aligned.m8n8.x4.shared.b16 {%0,%1,%2,%3}, [%4];"
        : "=r"(r[0]), "=r"(r[1]), "=r"(r[2]), "=r"(r[3]) : "r"(a));
}
__device__ __forceinline__ void ldsm_x2(uint32_t* r, uint32_t a) {
    asm volatile("ldmatrix.sync.aligned.m8n8.x2.shared.b16 {%0,%1}, [%2];"
        : "=r"(r[0]), "=r"(r[1]) : "r"(a));
}
__device__ __forceinline__ void ldsm_x2t(uint32_t* r, uint32_t a) {
    asm volatile("ldmatrix.sync.aligned.m8n8.x2.trans.shared.b16 {%0,%1}, [%2];"
        : "=r"(r[0]), "=r"(r[1]) : "r"(a));
}

// ---------------------------------------------------------------------------
// bf16 split-precision GEMM: C = Ah@Bh + Ah@Bl + Al@Bh  (fp32 accum)
// Block 128x128, BK=32, 8 warps (2x4), cp.async 3-stage pipeline, ldmatrix.
// TRI: grid.x enumerates lower-triangle 128x128 tiles (causal scores).
// CAUSALK: clamp K loop to m0+BM (causal PV).
// ---------------------------------------------------------------------------
constexpr int BM = 128, BN = 128, BK = 32;
constexpr uint32_t OFF_AH = 0, OFF_AL = 8192, OFF_BH = 16384, OFF_BL = 24576;
constexpr uint32_t STAGE_BYTES = 32768;
constexpr int NSTAGE = 3;
constexpr uint32_t SMEM_BYTES = NSTAGE * STAGE_BYTES;   // 96 KB

__device__ __forceinline__ uint32_t pa_off(int m, int g) {
    int line = m >> 1;
    int q = ((m & 1) << 2) | g;
    return (uint32_t)((line << 7) + ((q ^ (line & 7)) << 4));
}
__device__ __forceinline__ uint32_t pb_off(int k, int ng) {
    int line = (k << 1) | (ng >> 3);
    int q = ng & 7;
    return (uint32_t)((line << 7) + ((q ^ (k & 7)) << 4));
}

template <bool TRANSB>
__device__ __forceinline__ void load_tiles(
    const bf16* __restrict__ Ah, const bf16* __restrict__ Al,
    const bf16* __restrict__ Bh, const bf16* __restrict__ Bl,
    int K, int N, int m0, int n0, int k0, uint32_t sbase, int tid)
{
    {
        int m = tid & 127;
        int gb = (tid >> 7) << 1;
#pragma unroll
        for (int it = 0; it < 2; it++) {
            int g = gb + it;
            long long go = (long long)(m0 + m) * K + k0 + g * 8;
            uint32_t po = pa_off(m, g);
            cp_async16(sbase + OFF_AH + po, Ah + go);
            cp_async16(sbase + OFF_AL + po, Al + go);
        }
    }
    if (TRANSB) {
        int n = tid & 127;
        int gb = (tid >> 7) << 1;
#pragma unroll
        for (int it = 0; it < 2; it++) {
            int g = gb + it;
            long long go = (long long)(n0 + n) * K + k0 + g * 8;
            uint32_t po = pa_off(n, g);
            cp_async16(sbase + OFF_BH + po, Bh + go);
            cp_async16(sbase + OFF_BL + po, Bl + go);
        }
    } else {
        int k = tid >> 3;
        int gb = (tid & 7) << 1;
#pragma unroll
        for (int it = 0; it < 2; it++) {
            int g = gb + it;
            long long go = (long long)(k0 + k) * N + n0 + g * 8;
            uint32_t po = pb_off(k, g);
            cp_async16(sbase + OFF_BH + po, Bh + go);
            cp_async16(sbase + OFF_BL + po, Bl + go);
        }
    }
}

template <bool TRANSB, bool RELU, bool BIAS, bool SPLIT_OUT, bool TRI, bool CAUSALK>
__global__ __launch_bounds__(256, 2) void gemm_bf3(
    const bf16* __restrict__ Ah, const bf16* __restrict__ Al,
    const bf16* __restrict__ Bh, const bf16* __restrict__ Bl,
    const float* __restrict__ bias,
    float* __restrict__ C, bf16* __restrict__ Ch, bf16* __restrict__ Cl,
    int M, int N, int K, int ldc,
    long long aO, long long aI, long long bO, long long bI,
    long long cO, long long cI, long long biasI, int innerB)
{
    const int z = blockIdx.z;
    const int outer = z / innerB;
    const int inner = z - outer * innerB;
    const long long ao = outer * aO + inner * aI;
    const long long bo = outer * bO + inner * bI;
    const long long co = outer * cO + inner * cI;
    Ah += ao; Al += ao;
    Bh += bo; Bl += bo;
    if (SPLIT_OUT) { Ch += co; Cl += co; } else { C += co; }
    const float* bp = BIAS ? (bias + inner * biasI) : nullptr;

    int m0, n0;
    if (TRI) {
        // lower-triangle tile enumeration: bx -> (i >= j)
        int bx = blockIdx.x;
        int i = 0;
        while ((((i + 1) * (i + 2)) >> 1) <= bx) i++;
        int j = bx - ((i * (i + 1)) >> 1);
        m0 = i * BM;
        n0 = j * BN;
    } else {
        m0 = blockIdx.y * BM;
        n0 = blockIdx.x * BN;
    }

    const int Keff = CAUSALK ? (m0 + BM < K ? m0 + BM : K) : K;
    const int nIter = Keff / BK;

    extern __shared__ char smem[];
    const uint32_t sbase = (uint32_t)__cvta_generic_to_shared(smem);

    const int tid = threadIdx.x;
    const int lane = tid & 31, warp = tid >> 5;
    const int wm = warp >> 2;
    const int wn = warp & 3;
    const int t4 = lane & 3, g8 = lane >> 2;

    const int rowA = lane & 15;
    const int kSelA = lane >> 4;
    const int lsel = lane & 15;

    float acc[16][4];
#pragma unroll
    for (int i = 0; i < 16; i++)
#pragma unroll
        for (int j = 0; j < 4; j++) acc[i][j] = 0.f;

    // prologue: stages 0,1
    load_tiles<TRANSB>(Ah, Al, Bh, Bl, K, N, m0, n0, 0, sbase, tid);
    cp_commit();
    if (nIter > 1) {
        load_tiles<TRANSB>(Ah, Al, Bh, Bl, K, N, m0, n0, BK, sbase + STAGE_BYTES, tid);
        cp_commit();
    }

    for (int i = 0; i < nIter; i++) {
        if (i + 2 <= nIter) cp_wait<1>(); else cp_wait<0>();
        __syncthreads();

        const uint32_t sa = sbase + (uint32_t)(i % NSTAGE) * STAGE_BYTES;

#pragma unroll
        for (int c = 0; c < 2; c++) {
            uint32_t ah[4][4], al[4][4];
#pragma unroll
            for (int mi = 0; mi < 4; mi++) {
                int m = wm * 64 + mi * 16 + rowA;
                int g = 2 * c + kSelA;
                uint32_t po = pa_off(m, g);
                ldsm_x4(ah[mi], sa + OFF_AH + po);
                ldsm_x4(al[mi], sa + OFF_AL + po);
            }
#pragma unroll
            for (int ni = 0; ni < 4; ni++) {
                uint32_t bh[2], bl[2];
                if (TRANSB) {
                    int n = wn * 32 + ni * 8 + (lsel & 7);
                    int g = 2 * c + (lsel >> 3);
                    uint32_t po = pa_off(n, g);
                    ldsm_x2(bh, sa + OFF_BH + po);
                    ldsm_x2(bl, sa + OFF_BL + po);
                } else {
                    int k = c * 16 + lsel;
                    int ng = wn * 4 + ni;
                    uint32_t po = pb_off(k, ng);
                    ldsm_x2t(bh, sa + OFF_BH + po);
                    ldsm_x2t(bl, sa + OFF_BL + po);
                }
#pragma unroll
                for (int mi = 0; mi < 4; mi++) {
                    mma16(acc[mi * 4 + ni], ah[mi], bh);
                    mma16(acc[mi * 4 + ni], ah[mi], bl);
                    mma16(acc[mi * 4 + ni], al[mi], bh);
                }
            }
        }
        __syncthreads();

        if (i + 2 < nIter) {
            load_tiles<TRANSB>(Ah, Al, Bh, Bl, K, N, m0, n0, (i + 2) * BK,
                               sbase + (uint32_t)((i + 2) % NSTAGE) * STAGE_BYTES, tid);
            cp_commit();
        }
    }

    // epilogue
#pragma unroll
    for (int mi = 0; mi < 4; mi++) {
#pragma unroll
        for (int ni = 0; ni < 4; ni++) {
            const float* a = acc[mi * 4 + ni];
            int row = m0 + wm * 64 + mi * 16 + g8;
            int col = n0 + wn * 32 + ni * 8 + t4 * 2;
            float b0 = 0.f, b1 = 0.f;
            if (BIAS) { b0 = bp[col]; b1 = bp[col + 1]; }
            float v0 = a[0] + b0, v1 = a[1] + b1;
            float v2 = a[2] + b0, v3 = a[3] + b1;
            if (RELU) {
                v0 = fmaxf(v0, 0.f); v1 = fmaxf(v1, 0.f);
                v2 = fmaxf(v2, 0.f); v3 = fmaxf(v3, 0.f);
            }
            if (SPLIT_OUT) {
                uint32_t h0, l0, h1, l1;
                split2(v0, v1, h0, l0);
                split2(v2, v3, h1, l1);
                *(uint32_t*)(Ch + (long long)row * ldc + col) = h0;
                *(uint32_t*)(Cl + (long long)row * ldc + col) = l0;
                *(uint32_t*)(Ch + (long long)(row + 8) * ldc + col) = h1;
                *(uint32_t*)(Cl + (long long)(row + 8) * ldc + col) = l1;
            } else {
                *(float2*)(C + (long long)row * ldc + col) = make_float2(v0, v1);
                *(float2*)(C + (long long)(row + 8) * ldc + col) = make_float2(v2, v3);
            }
        }
    }
}

// ---------------------------------------------------------------------------
// fp32 -> bf16 hi/lo split (weights)
// ---------------------------------------------------------------------------
__global__ void split_arr(const float4* __restrict__ src,
                          uint32_t* __restrict__ hi, uint32_t* __restrict__ lo,
                          long long n4)
{
    long long i = (long long)blockIdx.x * blockDim.x + threadIdx.x;
    if (i >= n4) return;
    float4 v = src[i];
    uint32_t h0, l0, h1, l1;
    split2(v.x, v.y, h0, l0);
    split2(v.z, v.w, h1, l1);
    hi[2 * i] = h0; hi[2 * i + 1] = h1;
    lo[2 * i] = l0; lo[2 * i + 1] = l1;
}

// ---------------------------------------------------------------------------
// Embedding gather
// ---------------------------------------------------------------------------
__global__ void embed_k(const int* __restrict__ tok, const float* __restrict__ emb,
                        float* __restrict__ x, bf16* __restrict__ xh, bf16* __restrict__ xl)
{
    int i = blockIdx.x * blockDim.x + threadIdx.x;
    if (i >= NT * D) return;
    int r = i / D;
    int d = i - r * D;
    float v = emb[(long long)tok[r] * D + d];
    x[i] = v;
    bf16 h = __float2bfloat16_rn(v);
    xh[i] = h;
    xl[i] = __float2bfloat16_rn(v - __bfloat162float(h));
}

// ---------------------------------------------------------------------------
// Causal softmax; zero-fill only up to the diagonal block boundary
// (PV clamps K to exactly that boundary).
// ---------------------------------------------------------------------------
__global__ void softmax_k(const float* __restrict__ sc,
                          bf16* __restrict__ ph, bf16* __restrict__ pl)
{
    const long long r = blockIdx.x;
    const int t = (int)(r & (T - 1));
    const float* row = sc + r * T;
    const int len = t + 1;
    const int lim = (len + 127) & ~127;
    __shared__ float buf[T];
    __shared__ float red[256];
    const int tid = threadIdx.x;

    float m = -1e30f;
    for (int s = tid; s < len; s += 256) {
        float v = row[s];
        buf[s] = v;
        m = fmaxf(m, v);
    }
    red[tid] = m;
    __syncthreads();
    for (int o = 128; o; o >>= 1) {
        if (tid < o) red[tid] = fmaxf(red[tid], red[tid + o]);
        __syncthreads();
    }
    m = red[0];
    __syncthreads();

    float sum = 0.f;
    for (int s = tid; s < len; s += 256) {
        float e = expf(buf[s] - m);
        buf[s] = e;
        sum += e;
    }
    red[tid] = sum;
    __syncthreads();
    for (int o = 128; o; o >>= 1) {
        if (tid < o) red[tid] += red[tid + o];
        __syncthreads();
    }
    const float inv = 1.f / red[0];
    bf16 zero = __float2bfloat16_rn(0.f);
    for (int s = tid; s < lim; s += 256) {
        if (s < len) {
            float v = buf[s] * inv;
            bf16 h = __float2bfloat16_rn(v);
            ph[r * T + s] = h;
            pl[r * T + s] = __float2bfloat16_rn(v - __bfloat162float(h));
        } else {
            ph[r * T + s] = zero;
            pl[r * T + s] = zero;
        }
    }
}

// ---------------------------------------------------------------------------
// out = LN(xin + a) * g + b; fp32 out + optional bf16 hi/lo planes.
// ---------------------------------------------------------------------------
__global__ void addln_k(const float* __restrict__ xin, const float* __restrict__ a,
                        const float* __restrict__ g, const float* __restrict__ b,
                        float* __restrict__ out,
                        bf16* __restrict__ oh, bf16* __restrict__ ol)
{
    const long long r = blockIdx.x;
    __shared__ float buf[D];
    __shared__ float red[256];
    const int tid = threadIdx.x;

    float s = 0.f;
    for (int d = tid; d < D; d += 256) {
        float v = xin[r * D + d];
        if (a) v += a[r * D + d];
        buf[d] = v;
        s += v;
    }
    red[tid] = s;
    __syncthreads();
    for (int o = 128; o; o >>= 1) {
        if (tid < o) red[tid] += red[tid + o];
        __syncthreads();
    }
    const float mean = red[0] * (1.f / D);
    __syncthreads();

    float vs = 0.f;
    for (int d = tid; d < D; d += 256) {
        float dv = buf[d] - mean;
        vs += dv * dv;
    }
    red[tid] = vs;
    __syncthreads();
    for (int o = 128; o; o >>= 1) {
        if (tid < o) red[tid] += red[tid + o];
        __syncthreads();
    }
    const float rstd = rsqrtf(red[0] * (1.f / D) + 1e-5f);
    for (int d = tid; d < D; d += 256) {
        float v = (buf[d] - mean) * rstd * g[d] + b[d];
        out[r * D + d] = v;
        if (oh) {
            bf16 h = __float2bfloat16_rn(v);
            oh[r * D + d] = h;
            ol[r * D + d] = __float2bfloat16_rn(v - __bfloat162float(h));
        }
    }
}

// ---------------------------------------------------------------------------
// Cross-entropy + output
// ---------------------------------------------------------------------------
__global__ void lossrow_k(const float* __restrict__ logits, const int* __restrict__ labels,
                          float* __restrict__ rowloss)
{
    const int r = blockIdx.x;
    const int tid = threadIdx.x;
    __shared__ float red[V];
    const float v = logits[(long long)r * V + tid];
    red[tid] = v;
    __syncthreads();
    for (int o = 64; o; o >>= 1) {
        if (tid < o) red[tid] = fmaxf(red[tid], red[tid + o]);
        __syncthreads();
    }
    const float m = red[0];
    __syncthreads();
    red[tid] = expf(v - m);
    __syncthreads();
    for (int o = 64; o; o >>= 1) {
        if (tid < o) red[tid] += red[tid + o];
        __syncthreads();
    }
    if (tid == 0) {
        int lab = labels[r];
        rowloss[r] = -(logits[(long long)r * V + lab] - m - logf(red[0]));
    }
}

__global__ void lossred_k(const float* __restrict__ rowloss, float* __restrict__ loss)
{
    __shared__ float red[1024];
    const int tid = threadIdx.x;
    float s = 0.f;
    for (int i = tid; i < NT; i += 1024) s += rowloss[i];
    red[tid] = s;
    __syncthreads();
    for (int o = 512; o; o >>= 1) {
        if (tid < o) red[tid] += red[tid + o];
        __syncthreads();
    }
    if (tid == 0) loss[0] = red[0] / (float)NT;
}

__global__ void writeout_k(const float* __restrict__ logits, const float* __restrict__ loss,
                           float* __restrict__ out, int out_size)
{
    int i = blockIdx.x * blockDim.x + threadIdx.x;
    if (i >= out_size) return;
    const int NL = NT * V;
    if (out_size >= NL) out[i] = (i < NL) ? logits[i] : loss[0];
    else out[i] = loss[0];
}

// ---------------------------------------------------------------------------
// Host orchestration
// ---------------------------------------------------------------------------
static inline void split_launch(const float* src, bf16* hi, bf16* lo, long long n) {
    long long n4 = n / 4;
    split_arr<<<(unsigned)((n4 + 255) / 256), 256>>>(
        (const float4*)src, (uint32_t*)hi, (uint32_t*)lo, n4);
}

extern "C" void kernel_launch(void* const* d_in, const int* in_sizes, int n_in,
                              void* d_out, int out_size)
{
    const int*   tokens = (const int*)d_in[0];
    const int*   labels = (const int*)d_in[1];
    const float* emb    = (const float*)d_in[2];
    const float* Wq     = (const float*)d_in[3];
    const float* bq     = (const float*)d_in[4];
    const float* Wk     = (const float*)d_in[5];
    const float* bk     = (const float*)d_in[6];
    const float* Wv     = (const float*)d_in[7];
    const float* bv     = (const float*)d_in[8];
    const float* Wo     = (const float*)d_in[9];
    const float* bo     = (const float*)d_in[10];
    const float* ln1g   = (const float*)d_in[11];
    const float* ln1b   = (const float*)d_in[12];
    const float* W1     = (const float*)d_in[13];
    const float* b1     = (const float*)d_in[14];
    const float* W2     = (const float*)d_in[15];
    const float* b2     = (const float*)d_in[16];
    const float* ln2g   = (const float*)d_in[17];
    const float* ln2b   = (const float*)d_in[18];
    const float* lnfg   = (const float*)d_in[19];
    const float* lnfb   = (const float*)d_in[20];
    const float* Wout   = (const float*)d_in[21];
    const float* bout   = (const float*)d_in[22];

    float *x, *sc, *t2, *logits, *rowloss, *loss;
    cudaGetSymbolAddress((void**)&x, g_x);
    cudaGetSymbolAddress((void**)&sc, g_sc);
    cudaGetSymbolAddress((void**)&t2, g_t2);
    cudaGetSymbolAddress((void**)&logits, g_logits);
    cudaGetSymbolAddress((void**)&rowloss, g_rowloss);
    cudaGetSymbolAddress((void**)&loss, g_loss);

    bf16 *xh,*xl,*qh,*ql,*kh,*kl,*vh,*vl,*ph,*pl,*och,*ocl,*h1h,*h1l,*xfh,*xfl;
    cudaGetSymbolAddress((void**)&xh, g_xh);   cudaGetSymbolAddress((void**)&xl, g_xl);
    cudaGetSymbolAddress((void**)&qh, g_qh);   cudaGetSymbolAddress((void**)&ql, g_ql);
    cudaGetSymbolAddress((void**)&kh, g_kh);   cudaGetSymbolAddress((void**)&kl, g_kl);
    cudaGetSymbolAddress((void**)&vh, g_vh);   cudaGetSymbolAddress((void**)&vl, g_vl);
    cudaGetSymbolAddress((void**)&ph, g_ph);   cudaGetSymbolAddress((void**)&pl, g_pl);
    cudaGetSymbolAddress((void**)&och, g_och); cudaGetSymbolAddress((void**)&ocl, g_ocl);
    cudaGetSymbolAddress((void**)&h1h, g_h1h); cudaGetSymbolAddress((void**)&h1l, g_h1l);
    cudaGetSymbolAddress((void**)&xfh, g_xfh); cudaGetSymbolAddress((void**)&xfl, g_xfl);

    bf16 *wqh,*wql,*wkh,*wkl,*wvh,*wvl,*woh,*wol,*w1h,*w1l,*w2h,*w2l,*wouth,*woutl;
    cudaGetSymbolAddress((void**)&wqh, g_wqh); cudaGetSymbolAddress((void**)&wql, g_wql);
    cudaGetSymbolAddress((void**)&wkh, g_wkh); cudaGetSymbolAddress((void**)&wkl, g_wkl);
    cudaGetSymbolAddress((void**)&wvh, g_wvh); cudaGetSymbolAddress((void**)&wvl, g_wvl);
    cudaGetSymbolAddress((void**)&woh, g_woh); cudaGetSymbolAddress((void**)&wol, g_wol);
    cudaGetSymbolAddress((void**)&w1h, g_w1h); cudaGetSymbolAddress((void**)&w1l, g_w1l);
    cudaGetSymbolAddress((void**)&w2h, g_w2h); cudaGetSymbolAddress((void**)&w2l, g_w2l);
    cudaGetSymbolAddress((void**)&wouth, g_wouth); cudaGetSymbolAddress((void**)&woutl, g_woutl);

    cudaFuncSetAttribute(gemm_bf3<false,false,true,true,false,false>,
                         cudaFuncAttributeMaxDynamicSharedMemorySize, SMEM_BYTES);
    cudaFuncSetAttribute(gemm_bf3<true,false,false,false,true,false>,
                         cudaFuncAttributeMaxDynamicSharedMemorySize, SMEM_BYTES);
    cudaFuncSetAttribute(gemm_bf3<false,false,false,true,false,true>,
                         cudaFuncAttributeMaxDynamicSharedMemorySize, SMEM_BYTES);
    cudaFuncSetAttribute(gemm_bf3<false,false,true,false,false,false>,
                         cudaFuncAttributeMaxDynamicSharedMemorySize, SMEM_BYTES);
    cudaFuncSetAttribute(gemm_bf3<false,true,true,true,false,false>,
                         cudaFuncAttributeMaxDynamicSharedMemorySize, SMEM_BYTES);

    // Launch order chosen so launch #6 (ncu -s 5 -c 1) is the QKV GEMM.
    // 1. embedding gather
    embed_k<<<(NT * D + 255) / 256, 256>>>(tokens, emb, x, xh, xl);
    // 2-5. weight splits needed before the first GEMM
    split_launch(Wq, wqh, wql, WQKV);
    split_launch(Wk, wkh, wkl, WQKV);
    split_launch(Wv, wvh, wvl, WQKV);
    split_launch(Wo, woh, wol, WWO);

    const long long DD = (long long)D * D;
    const int TRI_TILES = (T / BM) * (T / BM + 1) / 2;   // 36

    for (int l = 0; l < L; l++) {
        const long long wOff = (long long)l * H * DD;
        const long long bOff = (long long)l * H * D;

        // 6. Q projection (profiled launch)
        dim3 gqkv(D / BN, T / BM, B * H);
        gemm_bf3<false,false,true,true,false,false><<<gqkv, 256, SMEM_BYTES>>>(
            xh, xl, wqh + wOff, wql + wOff, bq + bOff,
            nullptr, qh, ql, T, D, D, D,
            (long long)T * D, 0, 0, DD,
            (long long)H * T * D, (long long)T * D, D, H);
        if (l == 0) {
            // remaining weight splits (not needed until FFN / logits)
            split_launch(W1, w1h, w1l, WW1);
            split_launch(W2, w2h, w2l, WW2);
            split_launch(Wout, wouth, woutl, WOUT);
        }
        gemm_bf3<false,false,true,true,false,false><<<gqkv, 256, SMEM_BYTES>>>(
            xh, xl, wkh + wOff, wkl + wOff, bk + bOff,
            nullptr, kh, kl, T, D, D, D,
            (long long)T * D, 0, 0, DD,
            (long long)H * T * D, (long long)T * D, D, H);
        gemm_bf3<false,false,true,true,false,false><<<gqkv, 256, SMEM_BYTES>>>(
            xh, xl, wvh + wOff, wvl + wOff, bv + bOff,
            nullptr, vh, vl, T, D, D, D,
            (long long)T * D, 0, 0, DD,
            (long long)H * T * D, (long long)T * D, D, H);

        // scores = Q @ K^T, lower-triangle tiles only
        dim3 gsc(TRI_TILES, 1, B * H);
        gemm_bf3<true,false,false,false,true,false><<<gsc, 256, SMEM_BYTES>>>(
            qh, ql, kh, kl, nullptr,
            sc, nullptr, nullptr, T, T, D, T,
            (long long)T * D, 0, (long long)T * D, 0,
            (long long)T * T, 0, 0, 1);

        // causal softmax -> split P (zero fill to diagonal block only)
        softmax_k<<<B * H * T, 256>>>(sc, ph, pl);

        // O = P @ V with K clamped to m0+BM (causal)
        dim3 go(D / BN, T / BM, B * H);
        gemm_bf3<false,false,false,true,false,true><<<go, 256, SMEM_BYTES>>>(
            ph, pl, vh, vl, nullptr,
            nullptr, och, ocl, T, D, T, HD,
            (long long)H * T * T, (long long)T * T,
            (long long)H * T * D, (long long)T * D,
            (long long)T * HD, D, 0, H);

        // attn out projection
        dim3 gwo(D / BN, NT / BM, 1);
        gemm_bf3<false,false,true,false,false,false><<<gwo, 256, SMEM_BYTES>>>(
            och, ocl, woh + (long long)l * HD * D, wol + (long long)l * HD * D,
            bo + (long long)l * D,
            t2, nullptr, nullptr, NT, D, HD, D, 0, 0, 0, 0, 0, 0, 0, 1);

        // x = LN(x + attn)
        addln_k<<<NT, 256>>>(x, t2, ln1g + (long long)l * D, ln1b + (long long)l * D,
                             x, xh, xl);

        // FFN1 (+relu)
        dim3 gf1(DFF / BN, NT / BM, 1);
        gemm_bf3<false,true,true,true,false,false><<<gf1, 256, SMEM_BYTES>>>(
            xh, xl, w1h + (long long)l * D * DFF, w1l + (long long)l * D * DFF,
            b1 + (long long)l * DFF,
            nullptr, h1h, h1l, NT, DFF, D, DFF, 0, 0, 0, 0, 0, 0, 0, 1);

        // FFN2
        dim3 gf2(D / BN, NT / BM, 1);
        gemm_bf3<false,false,true,false,false,false><<<gf2, 256, SMEM_BYTES>>>(
            h1h, h1l, w2h + (long long)l * DFF * D, w2l + (long long)l * DFF * D,
            b2 + (long long)l * D,
            t2, nullptr, nullptr, NT, D, DFF, D, 0, 0, 0, 0, 0, 0, 0, 1);

        // x = LN(x + f)
        addln_k<<<NT, 256>>>(x, t2, ln2g + (long long)l * D, ln2b + (long long)l * D,
                             x, xh, xl);
    }

    // final LN -> split xf
    addln_k<<<NT, 256>>>(x, nullptr, lnfg, lnfb, t2, xfh, xfl);

    // logits
    dim3 glg(V / BN, NT / BM, 1);
    gemm_bf3<false,false,true,false,false,false><<<glg, 256, SMEM_BYTES>>>(
        xfh, xfl, wouth, woutl, bout,
        logits, nullptr, nullptr, NT, V, D, V, 0, 0, 0, 0, 0, 0, 0, 1);

    // loss
    lossrow_k<<<NT, V>>>(logits, labels, rowloss);
    lossred_k<<<1, 1024>>>(rowloss, loss);

    // output
    writeout_k<<<(out_size + 255) / 256, 256>>>(logits, loss, (float*)d_out, out_size);
}